// round 1
// baseline (speedup 1.0000x reference)
#include <cuda_runtime.h>
#include <math.h>

// Problem constants
#define M_TOK 8192          // B*S = 4*2048 tokens
#define DD    1024          // d_model
#define FF    4096          // d_ff
#define EE    4             // experts
#define N1    (EE*FF)       // 16384 = fused hidden width
#define SMASK 2047          // S-1 (S=2048, power of two)

// Scratch (allocation-free rule: __device__ globals)
__device__ float g_H[(size_t)M_TOK * N1];   // 512 MB hidden activations
__device__ float g_c[M_TOK * EE];           // per-token per-expert coefficients

// ---------------------------------------------------------------------------
// Kernel 1: per-token uncertainty -> expert coefficients
// c[t][e] = (k >= i_e) ? u / i_e : 0,  i_e = ((e - s) & 3) + 1
// ---------------------------------------------------------------------------
__global__ __launch_bounds__(256) void coeff_kernel(
    const float* __restrict__ x,
    const float* __restrict__ Wu,
    const float* __restrict__ bu)
{
    int t    = blockIdx.x * (blockDim.x >> 5) + (threadIdx.x >> 5);
    int lane = threadIdx.x & 31;
    if (t >= M_TOK) return;

    const float4* xr = (const float4*)(x + (size_t)t * DD);
    const float4* wr = (const float4*)Wu;
    float sum = 0.f;
#pragma unroll
    for (int i = lane; i < DD / 4; i += 32) {
        float4 a = xr[i], b = wr[i];
        sum += a.x * b.x + a.y * b.y + a.z * b.z + a.w * b.w;
    }
#pragma unroll
    for (int o = 16; o; o >>= 1) sum += __shfl_xor_sync(0xffffffffu, sum, o);

    if (lane == 0) {
        float z = sum + bu[0];
        float u = 1.f / (1.f + expf(-z));
        int   k = (int)ceilf(u * (float)EE);
        k = k < 1 ? 1 : (k > EE ? EE : k);
        int s = t & SMASK;
#pragma unroll
        for (int e = 0; e < EE; e++) {
            int ie = ((e - s) & 3) + 1;          // pass index touching expert e
            g_c[t * EE + e] = (k >= ie) ? (u / (float)ie) : 0.f;
        }
    }
}

// ---------------------------------------------------------------------------
// Tiled SGEMM, 128x128x8 block tile, 8x8 per-thread tile, 256 threads.
// MODE 1: C=g_H, A=x [8192,1024], B=W1 (per-expert base), epilogue relu+bias*c
// MODE 2: C=out, A=g_H [8192,16384], B=W2 flat [16384,1024], epilogue +Σc_e*b2
// All dims divisible by the tiles -> no bounds checks.
// ---------------------------------------------------------------------------
template <int MODE>
__global__ __launch_bounds__(256) void sgemm_kernel(
    const float* __restrict__ A,
    const float* __restrict__ B,
    float* __restrict__ C,
    int K, int N,
    const float* __restrict__ bias)   // b1 (MODE1) or b2 (MODE2)
{
    const int BM = 128, BN = 128, BK = 8;
    __shared__ float As[BK][BM];
    __shared__ float Bs[BK][BN];

    int tid = threadIdx.x;
    int bm  = blockIdx.y * BM;
    int bn  = blockIdx.x * BN;

    // Expert id + B base pointer / leading dim
    int e_blk = 0;
    const float* Bbase;
    size_t ldb;
    if (MODE == 1) {
        e_blk = (bn >> 12);                              // bn / 4096
        Bbase = B + (size_t)e_blk * DD * FF + (bn & (FF - 1));
        ldb   = FF;
    } else {
        Bbase = B + bn;
        ldb   = (size_t)N;
    }

    // Global-load assignments: one float4 of A and one float4 of B per thread
    int arow = tid >> 1, acol4 = (tid & 1) * 4;          // A tile: 128 x 8
    int brow = tid >> 5, bcol4 = (tid & 31) * 4;         // B tile: 8 x 128
    const float* Aptr = A + (size_t)(bm + arow) * K + acol4;
    const float* Bptr = Bbase + (size_t)brow * ldb + bcol4;

    int tx = tid & 15, ty = tid >> 4;                    // 16x16 thread grid
    float acc[8][8];
#pragma unroll
    for (int i = 0; i < 8; i++)
#pragma unroll
        for (int j = 0; j < 8; j++) acc[i][j] = 0.f;

    float4 av = *(const float4*)(Aptr);
    float4 bv = *(const float4*)(Bptr);

    for (int k0 = 0; k0 < K; k0 += BK) {
        // commit prefetched tile to smem (A transposed)
        As[acol4 + 0][arow] = av.x;
        As[acol4 + 1][arow] = av.y;
        As[acol4 + 2][arow] = av.z;
        As[acol4 + 3][arow] = av.w;
        *(float4*)&Bs[brow][bcol4] = bv;
        __syncthreads();

        // prefetch next tile into registers
        if (k0 + BK < K) {
            av = *(const float4*)(Aptr + (k0 + BK));
            bv = *(const float4*)(Bptr + (size_t)(k0 + BK) * ldb);
        }

#pragma unroll
        for (int kk = 0; kk < BK; kk++) {
            float a[8], b[8];
            *(float4*)(a)     = *(float4*)&As[kk][ty * 8];
            *(float4*)(a + 4) = *(float4*)&As[kk][ty * 8 + 4];
            *(float4*)(b)     = *(float4*)&Bs[kk][tx * 8];
            *(float4*)(b + 4) = *(float4*)&Bs[kk][tx * 8 + 4];
#pragma unroll
            for (int i = 0; i < 8; i++)
#pragma unroll
                for (int j = 0; j < 8; j++)
                    acc[i][j] = fmaf(a[i], b[j], acc[i][j]);
        }
        __syncthreads();
    }

    // ------------------------- epilogue -------------------------
    if (MODE == 1) {
        // bias for the 8 columns this thread owns (constant over rows)
        int f0 = (bn & (FF - 1)) + tx * 8;
        float brs[8];
        *(float4*)(brs)     = *(const float4*)(bias + (size_t)e_blk * FF + f0);
        *(float4*)(brs + 4) = *(const float4*)(bias + (size_t)e_blk * FF + f0 + 4);
#pragma unroll
        for (int i = 0; i < 8; i++) {
            int row = bm + ty * 8 + i;
            float cv = g_c[row * EE + e_blk];
            float out[8];
#pragma unroll
            for (int j = 0; j < 8; j++) {
                float v = acc[i][j] + brs[j];
                out[j] = fmaxf(v, 0.f) * cv;
            }
            float* cp = C + (size_t)row * N1 + bn + tx * 8;
            *(float4*)(cp)     = *(float4*)(out);
            *(float4*)(cp + 4) = *(float4*)(out + 4);
        }
    } else {
        int col0 = bn + tx * 8;
#pragma unroll
        for (int i = 0; i < 8; i++) {
            int row = bm + ty * 8 + i;
            float4 cc = *(const float4*)&g_c[row * EE];
            float out[8];
#pragma unroll
            for (int j = 0; j < 8; j++) {
                int col = col0 + j;
                float v = acc[i][j];
                v = fmaf(cc.x, bias[0 * DD + col], v);
                v = fmaf(cc.y, bias[1 * DD + col], v);
                v = fmaf(cc.z, bias[2 * DD + col], v);
                v = fmaf(cc.w, bias[3 * DD + col], v);
                out[j] = v;
            }
            float* cp = C + (size_t)row * DD + col0;
            *(float4*)(cp)     = *(float4*)(out);
            *(float4*)(cp + 4) = *(float4*)(out + 4);
        }
    }
}

// ---------------------------------------------------------------------------
// kernel_launch: coeff -> GEMM1(relu+scale) -> GEMM2(+bias mix)
// Inputs (metadata order): x, W1, b1, W2, b2, Wu, bu
// ---------------------------------------------------------------------------
extern "C" void kernel_launch(void* const* d_in, const int* in_sizes, int n_in,
                              void* d_out, int out_size)
{
    const float* x  = (const float*)d_in[0];
    const float* W1 = (const float*)d_in[1];
    const float* b1 = (const float*)d_in[2];
    const float* W2 = (const float*)d_in[3];
    const float* b2 = (const float*)d_in[4];
    const float* Wu = (const float*)d_in[5];
    const float* bu = (const float*)d_in[6];
    float* out = (float*)d_out;

    float* H;
    float* cbuf;
    cudaGetSymbolAddress((void**)&H, g_H);
    cudaGetSymbolAddress((void**)&cbuf, g_c);
    (void)cbuf; (void)in_sizes; (void)n_in; (void)out_size;

    // 1) coefficients: 8 warps/block, one warp per token
    coeff_kernel<<<M_TOK / 8, 256>>>(x, Wu, bu);

    // 2) GEMM1: [8192,1024] x [1024, 16384(=4 experts x 4096)] -> g_H
    {
        dim3 grid(N1 / 128, M_TOK / 128);
        sgemm_kernel<1><<<grid, 256>>>(x, W1, H, DD, N1, b1);
    }

    // 3) GEMM2: [8192,16384] x [16384,1024] -> out
    {
        dim3 grid(DD / 128, M_TOK / 128);
        sgemm_kernel<2><<<grid, 256>>>(H, W2, out, N1, DD, b2);
    }
}

// round 3
// speedup vs baseline: 2.9313x; 2.9313x over previous
#include <cuda_runtime.h>
#include <cuda_bf16.h>
#include <math.h>
#include <stdint.h>

// ---------------- problem constants ----------------
#define M_TOK 8192
#define DD    1024
#define FF    4096
#define EE    4
#define N1    16384
#define SMASK 2047

// ---------------- scratch (__device__ globals; no allocs allowed) ----------
__device__ float           g_c [M_TOK * EE];
__device__ __nv_bfloat16   g_xh[(size_t)M_TOK * DD];
__device__ __nv_bfloat16   g_xl[(size_t)M_TOK * DD];
__device__ __nv_bfloat16   g_w1h[(size_t)N1 * DD];
__device__ __nv_bfloat16   g_w1l[(size_t)N1 * DD];
__device__ __nv_bfloat16   g_w2h[(size_t)DD * N1];
__device__ __nv_bfloat16   g_w2l[(size_t)DD * N1];
__device__ __nv_bfloat16   g_Hh[(size_t)M_TOK * N1];
__device__ __nv_bfloat16   g_Hl[(size_t)M_TOK * N1];

// ---------------- helpers ----------------
__device__ __forceinline__ uint32_t smem_u32(const void* p) {
    uint32_t a;
    asm("{ .reg .u64 t; cvta.to.shared.u64 t, %1; cvt.u32.u64 %0, t; }" : "=r"(a) : "l"(p));
    return a;
}
#define CP16(sm, g)   asm volatile("cp.async.cg.shared.global [%0], [%1], 16;" :: "r"(sm), "l"(g) : "memory")
#define CP_COMMIT()   asm volatile("cp.async.commit_group;" ::: "memory")
#define CP_WAIT(n)    asm volatile("cp.async.wait_group %0;" :: "n"(n) : "memory")

#define LDMX4(r, a) asm volatile( \
    "ldmatrix.sync.aligned.m8n8.x4.shared.b16 {%0,%1,%2,%3}, [%4];" \
    : "=r"((r)[0]), "=r"((r)[1]), "=r"((r)[2]), "=r"((r)[3]) : "r"(a))
#define LDMX2(r, a) asm volatile( \
    "ldmatrix.sync.aligned.m8n8.x2.shared.b16 {%0,%1}, [%2];" \
    : "=r"((r)[0]), "=r"((r)[1]) : "r"(a))
#define MMA16816(d, a, b) asm volatile( \
    "mma.sync.aligned.m16n8k16.row.col.f32.bf16.bf16.f32 " \
    "{%0,%1,%2,%3}, {%4,%5,%6,%7}, {%8,%9}, {%0,%1,%2,%3};" \
    : "+f"((d)[0]), "+f"((d)[1]), "+f"((d)[2]), "+f"((d)[3]) \
    : "r"((a)[0]), "r"((a)[1]), "r"((a)[2]), "r"((a)[3]), "r"((b)[0]), "r"((b)[1]))

// tile layout: 128 rows x 64B (32 bf16). physical: pairs of rows packed into
// 128B lines, xor-swizzled so ldmatrix (8 rows @ same 16B chunk) is
// conflict-free. row in [0,128), cb in {0,16,32,48} bytes.
__device__ __forceinline__ uint32_t tile_addr(uint32_t base, int row, int cb) {
    uint32_t off = ((uint32_t)(row >> 1) << 7) + ((uint32_t)(row & 1) << 6) + (uint32_t)cb;
    return base + (off ^ (((uint32_t)(row >> 1) & 7u) << 4));
}

__device__ __forceinline__ void split2(float v, __nv_bfloat16& h, __nv_bfloat16& l) {
    h = __float2bfloat16(v);
    l = __float2bfloat16(v - __bfloat162float(h));
}

// ---------------------------------------------------------------------------
// coeff kernel
// ---------------------------------------------------------------------------
__global__ __launch_bounds__(256) void coeff_kernel(
    const float* __restrict__ x, const float* __restrict__ Wu,
    const float* __restrict__ bu)
{
    int t = blockIdx.x * 8 + (threadIdx.x >> 5);
    int lane = threadIdx.x & 31;
    if (t >= M_TOK) return;
    const float4* xr = (const float4*)(x + (size_t)t * DD);
    const float4* wr = (const float4*)Wu;
    float sum = 0.f;
#pragma unroll
    for (int i = lane; i < DD / 4; i += 32) {
        float4 a = xr[i], b = wr[i];
        sum += a.x * b.x + a.y * b.y + a.z * b.z + a.w * b.w;
    }
#pragma unroll
    for (int o = 16; o; o >>= 1) sum += __shfl_xor_sync(0xffffffffu, sum, o);
    if (lane == 0) {
        float z = sum + bu[0];
        float u = 1.f / (1.f + expf(-z));
        int k = (int)ceilf(u * (float)EE);
        k = k < 1 ? 1 : (k > EE ? EE : k);
        int s = t & SMASK;
#pragma unroll
        for (int e = 0; e < EE; e++) {
            int ie = ((e - s) & 3) + 1;
            g_c[t * EE + e] = (k >= ie) ? (u / (float)ie) : 0.f;
        }
    }
}

// ---------------------------------------------------------------------------
// fp32 -> bf16 hi/lo split (row-major copy)
// ---------------------------------------------------------------------------
__global__ __launch_bounds__(256) void convert_split_kernel(
    const float* __restrict__ in, __nv_bfloat16* __restrict__ oh,
    __nv_bfloat16* __restrict__ ol)
{
    size_t i = ((size_t)blockIdx.x * 256 + threadIdx.x) * 4;
    float4 v = *(const float4*)(in + i);
    float vv[4] = {v.x, v.y, v.z, v.w};
    __nv_bfloat16 h[4], l[4];
#pragma unroll
    for (int j = 0; j < 4; j++) split2(vv[j], h[j], l[j]);
    *(__nv_bfloat162*)(oh + i)     = __nv_bfloat162(h[0], h[1]);
    *(__nv_bfloat162*)(oh + i + 2) = __nv_bfloat162(h[2], h[3]);
    *(__nv_bfloat162*)(ol + i)     = __nv_bfloat162(l[0], l[1]);
    *(__nv_bfloat162*)(ol + i + 2) = __nv_bfloat162(l[2], l[3]);
}

// ---------------------------------------------------------------------------
// transpose [R,C] -> [C,R] + bf16 hi/lo split; blockIdx.z batches
// ---------------------------------------------------------------------------
__global__ __launch_bounds__(256) void transpose_split_kernel(
    const float* __restrict__ in, __nv_bfloat16* __restrict__ oh,
    __nv_bfloat16* __restrict__ ol, int R, int C)
{
    __shared__ float tile[32][33];
    size_t zoff = (size_t)blockIdx.z * R * C;
    int c0 = blockIdx.x * 32, r0 = blockIdx.y * 32;
    int tx = threadIdx.x, ty = threadIdx.y;
#pragma unroll
    for (int j = 0; j < 32; j += 8)
        tile[ty + j][tx] = in[zoff + (size_t)(r0 + ty + j) * C + c0 + tx];
    __syncthreads();
#pragma unroll
    for (int j = 0; j < 32; j += 8) {
        float v = tile[tx][ty + j];
        __nv_bfloat16 h, l;
        split2(v, h, l);
        size_t o = zoff + (size_t)(c0 + ty + j) * R + r0 + tx;
        oh[o] = h; ol[o] = l;
    }
}

// ---------------------------------------------------------------------------
// bf16 mma.sync GEMM, 128x128 CTA tile, BK=32, 3-term hi/lo split,
// 4-stage cp.async pipeline. 8 warps (2 M x 4 N), warp tile 64x32.
// MODE1: C=H (bf16 hi/lo), epilogue relu(acc+b1)*c_e -> split
// MODE2: C=out fp32, epilogue acc + sum_e c_e*b2[e]
// A: [*, KTOT] row-major (K contig). B: [*, KTOT] row-major (rows = N).
// ---------------------------------------------------------------------------
template <int MODE, int KTOT>
__global__ __launch_bounds__(256, 1) void gemm_kernel(
    const __nv_bfloat16* __restrict__ Ah, const __nv_bfloat16* __restrict__ Al,
    const __nv_bfloat16* __restrict__ Bh, const __nv_bfloat16* __restrict__ Bl,
    const float* __restrict__ bias,
    __nv_bfloat16* __restrict__ Ch, __nv_bfloat16* __restrict__ Cl,
    float* __restrict__ Co)
{
    extern __shared__ char smem[];
    uint32_t sbase = smem_u32(smem);
    const int tid = threadIdx.x;
    const int lane = tid & 31;
    const int wid = tid >> 5;
    const int wm = wid >> 2;          // 0..1 -> M offset wm*64
    const int wn = wid & 3;           // 0..3 -> N offset wn*32
    const int NK = KTOT / 32;

    int bm, bn;
    if (MODE == 1) { bm = blockIdx.x * 128; bn = blockIdx.y * 128; }
    else           { bn = blockIdx.x * 128; bm = blockIdx.y * 128; }

    // stage slot layout: slot*32768 + {Ah:0, Al:8192, Bh:16384, Bl:24576}
    auto load_chunk = [&](int k0, int slot) {
        uint32_t base = sbase + (uint32_t)slot * 32768u;
#pragma unroll
        for (int q = 0; q < 8; q++) {
            int lin = tid + q * 256;          // 0..2047
            int tl  = lin >> 9;               // 0..3
            int r   = (lin >> 2) & 127;
            int cq  = lin & 3;
            int cb  = cq * 16;
            int ke  = k0 + cq * 8;
            const __nv_bfloat16* src;
            if      (tl == 0) src = Ah + (size_t)(bm + r) * KTOT + ke;
            else if (tl == 1) src = Al + (size_t)(bm + r) * KTOT + ke;
            else if (tl == 2) src = Bh + (size_t)(bn + r) * KTOT + ke;
            else              src = Bl + (size_t)(bn + r) * KTOT + ke;
            CP16(tile_addr(base + (uint32_t)tl * 8192u, r, cb), src);
        }
        CP_COMMIT();
    };

    float acc[4][4][4];
#pragma unroll
    for (int mi = 0; mi < 4; mi++)
#pragma unroll
        for (int ni = 0; ni < 4; ni++)
#pragma unroll
            for (int j = 0; j < 4; j++) acc[mi][ni][j] = 0.f;

    load_chunk(0, 0);
    load_chunk(32, 1);
    load_chunk(64, 2);

    // ldmatrix lane address components (constant per thread)
    const int a_row = (lane & 15);                 // + wm*64 + mi*16
    const int a_cbo = ((lane >> 4) & 1) * 16;      // + ks*32
    const int bll   = lane & 15;
    const int b_row = (bll & 7);                   // + wn*32 + ni*8
    const int b_cbo = ((bll >> 3) & 1) * 16;       // + ks*32

    for (int i = 0; i < NK; i++) {
        CP_WAIT(2);
        __syncthreads();
        if (i + 3 < NK) load_chunk((i + 3) * 32, (i + 3) & 3);

        uint32_t base = sbase + (uint32_t)(i & 3) * 32768u;
        uint32_t bAh = base, bAl = base + 8192u, bBh = base + 16384u, bBl = base + 24576u;

#pragma unroll
        for (int ks = 0; ks < 2; ks++) {
            int kb = ks * 32;
            uint32_t ah[4][4], al[4][4], bh[4][2], bl[4][2];
#pragma unroll
            for (int mi = 0; mi < 4; mi++) {
                int r = wm * 64 + mi * 16 + a_row;
                LDMX4(ah[mi], tile_addr(bAh, r, kb + a_cbo));
                LDMX4(al[mi], tile_addr(bAl, r, kb + a_cbo));
            }
#pragma unroll
            for (int ni = 0; ni < 4; ni++) {
                int r = wn * 32 + ni * 8 + b_row;
                LDMX2(bh[ni], tile_addr(bBh, r, kb + b_cbo));
                LDMX2(bl[ni], tile_addr(bBl, r, kb + b_cbo));
            }
#pragma unroll
            for (int mi = 0; mi < 4; mi++)
#pragma unroll
                for (int ni = 0; ni < 4; ni++) MMA16816(acc[mi][ni], ah[mi], bh[ni]);
#pragma unroll
            for (int mi = 0; mi < 4; mi++)
#pragma unroll
                for (int ni = 0; ni < 4; ni++) MMA16816(acc[mi][ni], ah[mi], bl[ni]);
#pragma unroll
            for (int mi = 0; mi < 4; mi++)
#pragma unroll
                for (int ni = 0; ni < 4; ni++) MMA16816(acc[mi][ni], al[mi], bh[ni]);
        }
    }
    CP_WAIT(0);
    __syncthreads();   // before smem reuse by epilogue

    // accumulator element (mi,ni,reg j): row = wm*64+mi*16+(lane>>2)+(j>>1)*8
    //                                    col = wn*32+ni*8+(lane&3)*2+(j&1)
    if (MODE == 1) {
        int e   = bn >> 12;
        int bnf = bn & (FF - 1);
        // bias for owned cols
        float bv[4][2];
#pragma unroll
        for (int ni = 0; ni < 4; ni++) {
            int c0 = wn * 32 + ni * 8 + (lane & 3) * 2;
            bv[ni][0] = bias[(size_t)e * FF + bnf + c0];
            bv[ni][1] = bias[(size_t)e * FF + bnf + c0 + 1];
        }
#pragma unroll
        for (int mi = 0; mi < 4; mi++)
#pragma unroll
            for (int h = 0; h < 2; h++) {
                int row = wm * 64 + mi * 16 + (lane >> 2) + h * 8;
                float cv = g_c[(bm + row) * EE + e];
#pragma unroll
                for (int ni = 0; ni < 4; ni++) {
                    int c0 = wn * 32 + ni * 8 + (lane & 3) * 2;
                    float v0 = fmaxf(acc[mi][ni][h * 2 + 0] + bv[ni][0], 0.f) * cv;
                    float v1 = fmaxf(acc[mi][ni][h * 2 + 1] + bv[ni][1], 0.f) * cv;
                    __nv_bfloat16 h0, l0, h1, l1;
                    split2(v0, h0, l0);
                    split2(v1, h1, l1);
                    *(__nv_bfloat162*)(smem + row * 256 + c0 * 2)         = __nv_bfloat162(h0, h1);
                    *(__nv_bfloat162*)(smem + 32768 + row * 256 + c0 * 2) = __nv_bfloat162(l0, l1);
                }
            }
        __syncthreads();
#pragma unroll
        for (int q = 0; q < 16; q++) {
            int lin = tid + q * 256;          // 0..4095
            int mat = lin >> 11;
            int l2  = lin & 2047;
            int r   = l2 >> 4;
            int cw  = l2 & 15;
            uint4 v = *(uint4*)(smem + mat * 32768 + r * 256 + cw * 16);
            __nv_bfloat16* dst = (mat == 0 ? Ch : Cl);
            *(uint4*)(dst + (size_t)(bm + r) * N1 + bn + cw * 8) = v;
        }
    } else {
        float bv[4][2][EE];
#pragma unroll
        for (int ni = 0; ni < 4; ni++) {
            int c0 = bn + wn * 32 + ni * 8 + (lane & 3) * 2;
#pragma unroll
            for (int e = 0; e < EE; e++) {
                bv[ni][0][e] = bias[e * DD + c0];
                bv[ni][1][e] = bias[e * DD + c0 + 1];
            }
        }
#pragma unroll
        for (int mi = 0; mi < 4; mi++)
#pragma unroll
            for (int h = 0; h < 2; h++) {
                int row = wm * 64 + mi * 16 + (lane >> 2) + h * 8;
                float4 cc = *(const float4*)&g_c[(bm + row) * EE];
                float c4[4] = {cc.x, cc.y, cc.z, cc.w};
#pragma unroll
                for (int ni = 0; ni < 4; ni++) {
                    int c0 = wn * 32 + ni * 8 + (lane & 3) * 2;
#pragma unroll
                    for (int j = 0; j < 2; j++) {
                        float v = acc[mi][ni][h * 2 + j];
#pragma unroll
                        for (int e = 0; e < EE; e++) v = fmaf(c4[e], bv[ni][j][e], v);
                        *(float*)(smem + row * 512 + (c0 + j) * 4) = v;
                    }
                }
            }
        __syncthreads();
#pragma unroll
        for (int q = 0; q < 16; q++) {
            int lin = tid + q * 256;          // 0..4095
            int r   = lin >> 5;
            int cw  = lin & 31;
            uint4 v = *(uint4*)(smem + r * 512 + cw * 16);
            *(uint4*)(Co + (size_t)(bm + r) * DD + bn + cw * 4) = v;
        }
    }
}

// ---------------------------------------------------------------------------
// launch. Inputs: x, W1, b1, W2, b2, Wu, bu
// ---------------------------------------------------------------------------
extern "C" void kernel_launch(void* const* d_in, const int* in_sizes, int n_in,
                              void* d_out, int out_size)
{
    const float* x  = (const float*)d_in[0];
    const float* W1 = (const float*)d_in[1];
    const float* b1 = (const float*)d_in[2];
    const float* W2 = (const float*)d_in[3];
    const float* b2 = (const float*)d_in[4];
    const float* Wu = (const float*)d_in[5];
    const float* bu = (const float*)d_in[6];
    float* out = (float*)d_out;
    (void)in_sizes; (void)n_in; (void)out_size;

    __nv_bfloat16 *xh, *xl, *w1h, *w1l, *w2h, *w2l, *Hh, *Hl;
    cudaGetSymbolAddress((void**)&xh,  g_xh);
    cudaGetSymbolAddress((void**)&xl,  g_xl);
    cudaGetSymbolAddress((void**)&w1h, g_w1h);
    cudaGetSymbolAddress((void**)&w1l, g_w1l);
    cudaGetSymbolAddress((void**)&w2h, g_w2h);
    cudaGetSymbolAddress((void**)&w2l, g_w2l);
    cudaGetSymbolAddress((void**)&Hh,  g_Hh);
    cudaGetSymbolAddress((void**)&Hl,  g_Hl);

    const int SMEM_GEMM = 4 * 32768;  // 128 KB
    static int attr_done = 0;
    cudaFuncSetAttribute(gemm_kernel<1, DD>,
                         cudaFuncAttributeMaxDynamicSharedMemorySize, SMEM_GEMM);
    cudaFuncSetAttribute(gemm_kernel<2, N1>,
                         cudaFuncAttributeMaxDynamicSharedMemorySize, SMEM_GEMM);
    (void)attr_done;

    coeff_kernel<<<M_TOK / 8, 256>>>(x, Wu, bu);

    convert_split_kernel<<<(M_TOK * DD) / (256 * 4), 256>>>(x, xh, xl);

    {   // W1 [E][D,F] -> [E*F, D] hi/lo
        dim3 grid(FF / 32, DD / 32, EE);
        transpose_split_kernel<<<grid, dim3(32, 8)>>>(W1, w1h, w1l, DD, FF);
    }
    {   // W2 [N1, D] -> [D, N1] hi/lo
        dim3 grid(DD / 32, N1 / 32, 1);
        transpose_split_kernel<<<grid, dim3(32, 8)>>>(W2, w2h, w2l, N1, DD);
    }

    {   // GEMM1: [8192,1024] x [1024,16384] -> H bf16 hi/lo (M fast for B reuse)
        dim3 grid(M_TOK / 128, N1 / 128);
        gemm_kernel<1, DD><<<grid, 256, SMEM_GEMM>>>(
            xh, xl, w1h, w1l, b1, Hh, Hl, nullptr);
    }
    {   // GEMM2: [8192,16384] x [16384,1024] -> out fp32 (N fast for A reuse)
        dim3 grid(DD / 128, M_TOK / 128);
        gemm_kernel<2, N1><<<grid, 256, SMEM_GEMM>>>(
            Hh, Hl, w2h, w2l, b2, nullptr, nullptr, out);
    }
}

// round 4
// speedup vs baseline: 4.6318x; 1.5801x over previous
#include <cuda_runtime.h>
#include <cuda_bf16.h>
#include <math.h>
#include <stdint.h>

// ---------------- problem constants ----------------
#define M_TOK 8192
#define DD    1024
#define FF    4096
#define EE    4
#define N1    16384
#define SMASK 2047

// ---------------- scratch (__device__ globals; no allocs allowed) ----------
__device__ float           g_c [M_TOK * EE];
__device__ int             g_cnt[EE];
__device__ int             g_list[EE * M_TOK];
__device__ int             g_pos[M_TOK * EE];
__device__ __nv_bfloat16   g_xh[(size_t)M_TOK * DD];
__device__ __nv_bfloat16   g_xl[(size_t)M_TOK * DD];
__device__ __nv_bfloat16   g_w1h[(size_t)N1 * DD];
__device__ __nv_bfloat16   g_w1l[(size_t)N1 * DD];
__device__ __nv_bfloat16   g_w2h[(size_t)DD * N1];
__device__ __nv_bfloat16   g_w2l[(size_t)DD * N1];
__device__ __nv_bfloat16   g_Hh[(size_t)EE * M_TOK * FF];   // per-expert compacted
__device__ __nv_bfloat16   g_Hl[(size_t)EE * M_TOK * FF];
__device__ float           g_y [(size_t)EE * M_TOK * DD];   // per-expert compacted fp32

// ---------------- helpers ----------------
__device__ __forceinline__ uint32_t smem_u32(const void* p) {
    uint32_t a;
    asm("{ .reg .u64 t; cvta.to.shared.u64 t, %1; cvt.u32.u64 %0, t; }" : "=r"(a) : "l"(p));
    return a;
}
#define CP16(sm, g)   asm volatile("cp.async.cg.shared.global [%0], [%1], 16;" :: "r"(sm), "l"(g) : "memory")
#define CP_COMMIT()   asm volatile("cp.async.commit_group;" ::: "memory")
#define CP_WAIT(n)    asm volatile("cp.async.wait_group %0;" :: "n"(n) : "memory")

#define LDMX4(r, a) asm volatile( \
    "ldmatrix.sync.aligned.m8n8.x4.shared.b16 {%0,%1,%2,%3}, [%4];" \
    : "=r"((r)[0]), "=r"((r)[1]), "=r"((r)[2]), "=r"((r)[3]) : "r"(a))
#define LDMX2(r, a) asm volatile( \
    "ldmatrix.sync.aligned.m8n8.x2.shared.b16 {%0,%1}, [%2];" \
    : "=r"((r)[0]), "=r"((r)[1]) : "r"(a))
#define MMA16816(d, a, b) asm volatile( \
    "mma.sync.aligned.m16n8k16.row.col.f32.bf16.bf16.f32 " \
    "{%0,%1,%2,%3}, {%4,%5,%6,%7}, {%8,%9}, {%0,%1,%2,%3};" \
    : "+f"((d)[0]), "+f"((d)[1]), "+f"((d)[2]), "+f"((d)[3]) \
    : "r"((a)[0]), "r"((a)[1]), "r"((a)[2]), "r"((a)[3]), "r"((b)[0]), "r"((b)[1]))

// 128 rows x 64B tile; row pairs packed into 128B lines, xor swizzle.
__device__ __forceinline__ uint32_t tile_addr(uint32_t base, int row, int cb) {
    uint32_t off = ((uint32_t)(row >> 1) << 7) + ((uint32_t)(row & 1) << 6) + (uint32_t)cb;
    return base + (off ^ (((uint32_t)(row >> 1) & 7u) << 4));
}
__device__ __forceinline__ void split2(float v, __nv_bfloat16& h, __nv_bfloat16& l) {
    h = __float2bfloat16(v);
    l = __float2bfloat16(v - __bfloat162float(h));
}

// ---------------------------------------------------------------------------
// coeff kernel
// ---------------------------------------------------------------------------
__global__ __launch_bounds__(256) void coeff_kernel(
    const float* __restrict__ x, const float* __restrict__ Wu,
    const float* __restrict__ bu)
{
    int t = blockIdx.x * 8 + (threadIdx.x >> 5);
    int lane = threadIdx.x & 31;
    if (t >= M_TOK) return;
    const float4* xr = (const float4*)(x + (size_t)t * DD);
    const float4* wr = (const float4*)Wu;
    float sum = 0.f;
#pragma unroll
    for (int i = lane; i < DD / 4; i += 32) {
        float4 a = xr[i], b = wr[i];
        sum += a.x * b.x + a.y * b.y + a.z * b.z + a.w * b.w;
    }
#pragma unroll
    for (int o = 16; o; o >>= 1) sum += __shfl_xor_sync(0xffffffffu, sum, o);
    if (lane == 0) {
        float z = sum + bu[0];
        float u = 1.f / (1.f + expf(-z));
        int k = (int)ceilf(u * (float)EE);
        k = k < 1 ? 1 : (k > EE ? EE : k);
        int s = t & SMASK;
#pragma unroll
        for (int e = 0; e < EE; e++) {
            int ie = ((e - s) & 3) + 1;
            g_c[t * EE + e] = (k >= ie) ? (u / (float)ie) : 0.f;
        }
    }
}

__global__ void init_cnt_kernel() {
    if (threadIdx.x < EE) g_cnt[threadIdx.x] = 0;
}

__global__ __launch_bounds__(256) void build_lists_kernel() {
    int t = blockIdx.x * 256 + threadIdx.x;
    if (t >= M_TOK) return;
#pragma unroll
    for (int e = 0; e < EE; e++) {
        if (g_c[t * EE + e] != 0.f) {
            int p = atomicAdd(&g_cnt[e], 1);
            g_list[e * M_TOK + p] = t;
            g_pos[t * EE + e] = p;
        }
    }
}

// ---------------------------------------------------------------------------
// fp32 -> bf16 hi/lo split
// ---------------------------------------------------------------------------
__global__ __launch_bounds__(256) void convert_split_kernel(
    const float* __restrict__ in, __nv_bfloat16* __restrict__ oh,
    __nv_bfloat16* __restrict__ ol)
{
    size_t i = ((size_t)blockIdx.x * 256 + threadIdx.x) * 4;
    float4 v = *(const float4*)(in + i);
    float vv[4] = {v.x, v.y, v.z, v.w};
    __nv_bfloat16 h[4], l[4];
#pragma unroll
    for (int j = 0; j < 4; j++) split2(vv[j], h[j], l[j]);
    *(__nv_bfloat162*)(oh + i)     = __nv_bfloat162(h[0], h[1]);
    *(__nv_bfloat162*)(oh + i + 2) = __nv_bfloat162(h[2], h[3]);
    *(__nv_bfloat162*)(ol + i)     = __nv_bfloat162(l[0], l[1]);
    *(__nv_bfloat162*)(ol + i + 2) = __nv_bfloat162(l[2], l[3]);
}

// ---------------------------------------------------------------------------
// transpose [R,C] -> [C,R] + hi/lo split; blockIdx.z batches
// ---------------------------------------------------------------------------
__global__ __launch_bounds__(256) void transpose_split_kernel(
    const float* __restrict__ in, __nv_bfloat16* __restrict__ oh,
    __nv_bfloat16* __restrict__ ol, int R, int C)
{
    __shared__ float tile[32][33];
    size_t zoff = (size_t)blockIdx.z * R * C;
    int c0 = blockIdx.x * 32, r0 = blockIdx.y * 32;
    int tx = threadIdx.x, ty = threadIdx.y;
#pragma unroll
    for (int j = 0; j < 32; j += 8)
        tile[ty + j][tx] = in[zoff + (size_t)(r0 + ty + j) * C + c0 + tx];
    __syncthreads();
#pragma unroll
    for (int j = 0; j < 32; j += 8) {
        float v = tile[tx][ty + j];
        __nv_bfloat16 h, l;
        split2(v, h, l);
        size_t o = zoff + (size_t)(c0 + ty + j) * R + r0 + tx;
        oh[o] = h; ol[o] = l;
    }
}

// ---------------------------------------------------------------------------
// sparse per-expert bf16 GEMM, 128x128 tile, BK=32, 3-term split, 4 stages.
// MODE1: A = x gathered by g_list[e], B = W1T_e, C = H_e (bf16 hi/lo),
//        epilogue relu(acc+b1_e)*c -> split.   grid (Mtile, Ntile=32, e)
// MODE2: A = H_e compacted, B = W2T_e, C = y_e fp32, plain store.
//        grid (Ntile=8, Mtile, e)
// Early exit when mtile >= ceil(n_e/128).
// ---------------------------------------------------------------------------
template <int MODE>
__global__ __launch_bounds__(256, 1) void gemm_kernel(
    const __nv_bfloat16* __restrict__ Ah, const __nv_bfloat16* __restrict__ Al,
    const __nv_bfloat16* __restrict__ Bh, const __nv_bfloat16* __restrict__ Bl,
    const float* __restrict__ bias,
    __nv_bfloat16* __restrict__ Ch, __nv_bfloat16* __restrict__ Cl,
    float* __restrict__ Yo)
{
    const int KTOT = (MODE == 1) ? DD : FF;
    const int NK   = KTOT / 32;

    extern __shared__ char smem[];
    uint32_t sbase = smem_u32(smem);
    int* sList = (int*)(smem + 131072);

    const int tid = threadIdx.x;
    const int lane = tid & 31;
    const int wid = tid >> 5;
    const int wm = wid >> 2;
    const int wn = wid & 3;

    const int e = blockIdx.z;
    const int n_e = g_cnt[e];
    const int mtiles = (n_e + 127) >> 7;
    const int mt = (MODE == 1) ? blockIdx.x : blockIdx.y;
    if (mt >= mtiles) return;
    const int bm = mt * 128;
    const int bn = ((MODE == 1) ? blockIdx.y : blockIdx.x) * 128;

    if (MODE == 1) {
        if (tid < 128) {
            int idx = bm + tid;
            sList[tid] = (idx < n_e) ? g_list[e * M_TOK + idx] : 0;
        }
        __syncthreads();
    }

    // stage slot layout: slot*32768 + {Ah:0, Al:8192, Bh:16384, Bl:24576}
    auto load_chunk = [&](int k0, int slot) {
        uint32_t base = sbase + (uint32_t)slot * 32768u;
#pragma unroll
        for (int q = 0; q < 8; q++) {
            int lin = tid + q * 256;
            int tl  = lin >> 9;
            int r   = (lin >> 2) & 127;
            int cq  = lin & 3;
            int cb  = cq * 16;
            int ke  = k0 + cq * 8;
            const __nv_bfloat16* src;
            if (MODE == 1) {
                if      (tl == 0) src = Ah + (size_t)sList[r] * DD + ke;
                else if (tl == 1) src = Al + (size_t)sList[r] * DD + ke;
                else if (tl == 2) src = Bh + ((size_t)e * FF + bn + r) * DD + ke;
                else              src = Bl + ((size_t)e * FF + bn + r) * DD + ke;
            } else {
                if      (tl == 0) src = Ah + (size_t)e * M_TOK * FF + (size_t)(bm + r) * FF + ke;
                else if (tl == 1) src = Al + (size_t)e * M_TOK * FF + (size_t)(bm + r) * FF + ke;
                else if (tl == 2) src = Bh + (size_t)(bn + r) * N1 + e * FF + ke;
                else              src = Bl + (size_t)(bn + r) * N1 + e * FF + ke;
            }
            CP16(tile_addr(base + (uint32_t)tl * 8192u, r, cb), src);
        }
        CP_COMMIT();
    };

    float acc[4][4][4];
#pragma unroll
    for (int mi = 0; mi < 4; mi++)
#pragma unroll
        for (int ni = 0; ni < 4; ni++)
#pragma unroll
            for (int j = 0; j < 4; j++) acc[mi][ni][j] = 0.f;

    load_chunk(0, 0);
    load_chunk(32, 1);
    load_chunk(64, 2);

    const int a_row = (lane & 15);
    const int a_cbo = ((lane >> 4) & 1) * 16;
    const int bll   = lane & 15;
    const int b_row = (bll & 7);
    const int b_cbo = ((bll >> 3) & 1) * 16;

    for (int i = 0; i < NK; i++) {
        CP_WAIT(2);
        __syncthreads();
        if (i + 3 < NK) load_chunk((i + 3) * 32, (i + 3) & 3);

        uint32_t base = sbase + (uint32_t)(i & 3) * 32768u;
        uint32_t bAh = base, bAl = base + 8192u, bBh = base + 16384u, bBl = base + 24576u;

#pragma unroll
        for (int ks = 0; ks < 2; ks++) {
            int kb = ks * 32;
            uint32_t ah[4][4], al[4][4], bh[4][2], bl[4][2];
#pragma unroll
            for (int mi = 0; mi < 4; mi++) {
                int r = wm * 64 + mi * 16 + a_row;
                LDMX4(ah[mi], tile_addr(bAh, r, kb + a_cbo));
                LDMX4(al[mi], tile_addr(bAl, r, kb + a_cbo));
            }
#pragma unroll
            for (int ni = 0; ni < 4; ni++) {
                int r = wn * 32 + ni * 8 + b_row;
                LDMX2(bh[ni], tile_addr(bBh, r, kb + b_cbo));
                LDMX2(bl[ni], tile_addr(bBl, r, kb + b_cbo));
            }
#pragma unroll
            for (int mi = 0; mi < 4; mi++)
#pragma unroll
                for (int ni = 0; ni < 4; ni++) MMA16816(acc[mi][ni], ah[mi], bh[ni]);
#pragma unroll
            for (int mi = 0; mi < 4; mi++)
#pragma unroll
                for (int ni = 0; ni < 4; ni++) MMA16816(acc[mi][ni], ah[mi], bl[ni]);
#pragma unroll
            for (int mi = 0; mi < 4; mi++)
#pragma unroll
                for (int ni = 0; ni < 4; ni++) MMA16816(acc[mi][ni], al[mi], bh[ni]);
        }
    }
    CP_WAIT(0);
    __syncthreads();

    // acc(mi,ni,j): row = wm*64+mi*16+(lane>>2)+(j>>1)*8, col = wn*32+ni*8+(lane&3)*2+(j&1)
    if (MODE == 1) {
        float bv[4][2];
#pragma unroll
        for (int ni = 0; ni < 4; ni++) {
            int c0 = wn * 32 + ni * 8 + (lane & 3) * 2;
            bv[ni][0] = bias[(size_t)e * FF + bn + c0];
            bv[ni][1] = bias[(size_t)e * FF + bn + c0 + 1];
        }
#pragma unroll
        for (int mi = 0; mi < 4; mi++)
#pragma unroll
            for (int h = 0; h < 2; h++) {
                int row = wm * 64 + mi * 16 + (lane >> 2) + h * 8;
                float cv = (bm + row < n_e) ? g_c[sList[row] * EE + e] : 0.f;
#pragma unroll
                for (int ni = 0; ni < 4; ni++) {
                    int c0 = wn * 32 + ni * 8 + (lane & 3) * 2;
                    float v0 = fmaxf(acc[mi][ni][h * 2 + 0] + bv[ni][0], 0.f) * cv;
                    float v1 = fmaxf(acc[mi][ni][h * 2 + 1] + bv[ni][1], 0.f) * cv;
                    __nv_bfloat16 h0, l0, h1, l1;
                    split2(v0, h0, l0);
                    split2(v1, h1, l1);
                    *(__nv_bfloat162*)(smem + row * 256 + c0 * 2)         = __nv_bfloat162(h0, h1);
                    *(__nv_bfloat162*)(smem + 32768 + row * 256 + c0 * 2) = __nv_bfloat162(l0, l1);
                }
            }
        __syncthreads();
#pragma unroll
        for (int q = 0; q < 16; q++) {
            int lin = tid + q * 256;
            int mat = lin >> 11;
            int l2  = lin & 2047;
            int r   = l2 >> 4;
            int cw  = l2 & 15;
            uint4 v = *(uint4*)(smem + mat * 32768 + r * 256 + cw * 16);
            __nv_bfloat16* dst = (mat == 0 ? Ch : Cl);
            *(uint4*)(dst + (size_t)e * M_TOK * FF + (size_t)(bm + r) * FF + bn + cw * 8) = v;
        }
    } else {
#pragma unroll
        for (int mi = 0; mi < 4; mi++)
#pragma unroll
            for (int h = 0; h < 2; h++) {
                int row = wm * 64 + mi * 16 + (lane >> 2) + h * 8;
#pragma unroll
                for (int ni = 0; ni < 4; ni++) {
                    int c0 = wn * 32 + ni * 8 + (lane & 3) * 2;
                    *(float*)(smem + row * 512 + c0 * 4)       = acc[mi][ni][h * 2 + 0];
                    *(float*)(smem + row * 512 + (c0 + 1) * 4) = acc[mi][ni][h * 2 + 1];
                }
            }
        __syncthreads();
#pragma unroll
        for (int q = 0; q < 16; q++) {
            int lin = tid + q * 256;
            int r   = lin >> 5;
            int cw  = lin & 31;
            uint4 v = *(uint4*)(smem + r * 512 + cw * 16);
            *(uint4*)(Yo + (size_t)e * M_TOK * DD + (size_t)(bm + r) * DD + bn + cw * 4) = v;
        }
    }
}

// ---------------------------------------------------------------------------
// final gather: out[t] = sum over active e of (y_e[pos] + c_e*b2_e)
// ---------------------------------------------------------------------------
__global__ __launch_bounds__(256) void gather_out_kernel(
    const float* __restrict__ y, const float* __restrict__ b2,
    float* __restrict__ out)
{
    int t = blockIdx.x;
    int d = threadIdx.x * 4;
    float acc0 = 0.f, acc1 = 0.f, acc2 = 0.f, acc3 = 0.f;
#pragma unroll
    for (int e = 0; e < EE; e++) {
        float c = g_c[t * EE + e];
        if (c != 0.f) {
            int pos = g_pos[t * EE + e];
            float4 vy = *(const float4*)(y + (size_t)e * M_TOK * DD + (size_t)pos * DD + d);
            float4 vb = *(const float4*)(b2 + e * DD + d);
            acc0 += vy.x + c * vb.x;
            acc1 += vy.y + c * vb.y;
            acc2 += vy.z + c * vb.z;
            acc3 += vy.w + c * vb.w;
        }
    }
    float4 o = {acc0, acc1, acc2, acc3};
    *(float4*)(out + (size_t)t * DD + d) = o;
}

// ---------------------------------------------------------------------------
// launch. Inputs: x, W1, b1, W2, b2, Wu, bu
// ---------------------------------------------------------------------------
extern "C" void kernel_launch(void* const* d_in, const int* in_sizes, int n_in,
                              void* d_out, int out_size)
{
    const float* x  = (const float*)d_in[0];
    const float* W1 = (const float*)d_in[1];
    const float* b1 = (const float*)d_in[2];
    const float* W2 = (const float*)d_in[3];
    const float* b2 = (const float*)d_in[4];
    const float* Wu = (const float*)d_in[5];
    const float* bu = (const float*)d_in[6];
    float* out = (float*)d_out;
    (void)in_sizes; (void)n_in; (void)out_size;

    __nv_bfloat16 *xh, *xl, *w1h, *w1l, *w2h, *w2l, *Hh, *Hl;
    float* y;
    cudaGetSymbolAddress((void**)&xh,  g_xh);
    cudaGetSymbolAddress((void**)&xl,  g_xl);
    cudaGetSymbolAddress((void**)&w1h, g_w1h);
    cudaGetSymbolAddress((void**)&w1l, g_w1l);
    cudaGetSymbolAddress((void**)&w2h, g_w2h);
    cudaGetSymbolAddress((void**)&w2l, g_w2l);
    cudaGetSymbolAddress((void**)&Hh,  g_Hh);
    cudaGetSymbolAddress((void**)&Hl,  g_Hl);
    cudaGetSymbolAddress((void**)&y,   g_y);

    const int SMEM_GEMM = 131072 + 512;
    cudaFuncSetAttribute(gemm_kernel<1>,
                         cudaFuncAttributeMaxDynamicSharedMemorySize, SMEM_GEMM);
    cudaFuncSetAttribute(gemm_kernel<2>,
                         cudaFuncAttributeMaxDynamicSharedMemorySize, SMEM_GEMM);

    coeff_kernel<<<M_TOK / 8, 256>>>(x, Wu, bu);
    init_cnt_kernel<<<1, 32>>>();
    build_lists_kernel<<<M_TOK / 256, 256>>>();

    convert_split_kernel<<<(M_TOK * DD) / (256 * 4), 256>>>(x, xh, xl);
    {   // W1 [E][D,F] -> [E*F, D] hi/lo
        dim3 grid(FF / 32, DD / 32, EE);
        transpose_split_kernel<<<grid, dim3(32, 8)>>>(W1, w1h, w1l, DD, FF);
    }
    {   // W2 [E*F, D] -> [D, E*F] hi/lo
        dim3 grid(DD / 32, N1 / 32, 1);
        transpose_split_kernel<<<grid, dim3(32, 8)>>>(W2, w2h, w2l, N1, DD);
    }

    {   // GEMM1 sparse: per-expert [n_e,1024] x [1024,4096] -> H_e hi/lo
        dim3 grid(M_TOK / 128, FF / 128, EE);   // Mtile fast (B-panel reuse)
        gemm_kernel<1><<<grid, 256, SMEM_GEMM>>>(
            xh, xl, w1h, w1l, b1, Hh, Hl, nullptr);
    }
    {   // GEMM2 sparse: per-expert [n_e,4096] x [4096,1024] -> y_e fp32
        dim3 grid(DD / 128, M_TOK / 128, EE);   // Ntile fast (A-panel reuse)
        gemm_kernel<2><<<grid, 256, SMEM_GEMM>>>(
            Hh, Hl, w2h, w2l, nullptr, nullptr, nullptr, y);
    }

    gather_out_kernel<<<M_TOK, 256>>>(y, b2, out);
}

// round 5
// speedup vs baseline: 6.3088x; 1.3621x over previous
#include <cuda_runtime.h>
#include <cuda_bf16.h>
#include <cuda_fp16.h>
#include <math.h>
#include <stdint.h>

// ---------------- problem constants ----------------
#define M_TOK 8192
#define DD    1024
#define FF    4096
#define EE    4
#define N1    16384
#define SMASK 2047

// ---------------- scratch (__device__ globals; no allocs allowed) ----------
__device__ float   g_c [M_TOK * EE];
__device__ int     g_cnt[EE];
__device__ int     g_list[EE * M_TOK];
__device__ int     g_pos[M_TOK * EE];
__device__ __half  g_xh[(size_t)M_TOK * DD];
__device__ __half  g_xl[(size_t)M_TOK * DD];
__device__ __half  g_w1[(size_t)N1 * DD];          // W1T fp16 (single)
__device__ __half  g_w2[(size_t)DD * N1];          // W2T fp16 (single)
__device__ __half  g_Hh[(size_t)EE * M_TOK * FF];  // per-expert compacted hi
__device__ __half  g_Hl[(size_t)EE * M_TOK * FF];  // per-expert compacted lo
__device__ float   g_y [(size_t)EE * M_TOK * DD];  // per-expert compacted fp32

// ---------------- helpers ----------------
__device__ __forceinline__ uint32_t smem_u32(const void* p) {
    uint32_t a;
    asm("{ .reg .u64 t; cvta.to.shared.u64 t, %1; cvt.u32.u64 %0, t; }" : "=r"(a) : "l"(p));
    return a;
}
#define CP16(sm, g)   asm volatile("cp.async.cg.shared.global [%0], [%1], 16;" :: "r"(sm), "l"(g) : "memory")
#define CP_COMMIT()   asm volatile("cp.async.commit_group;" ::: "memory")
#define CP_WAIT(n)    asm volatile("cp.async.wait_group %0;" :: "n"(n) : "memory")

#define LDMX4(r, a) asm volatile( \
    "ldmatrix.sync.aligned.m8n8.x4.shared.b16 {%0,%1,%2,%3}, [%4];" \
    : "=r"((r)[0]), "=r"((r)[1]), "=r"((r)[2]), "=r"((r)[3]) : "r"(a))
#define LDMX2(r, a) asm volatile( \
    "ldmatrix.sync.aligned.m8n8.x2.shared.b16 {%0,%1}, [%2];" \
    : "=r"((r)[0]), "=r"((r)[1]) : "r"(a))
#define MMA16816(d, a, b) asm volatile( \
    "mma.sync.aligned.m16n8k16.row.col.f32.f16.f16.f32 " \
    "{%0,%1,%2,%3}, {%4,%5,%6,%7}, {%8,%9}, {%0,%1,%2,%3};" \
    : "+f"((d)[0]), "+f"((d)[1]), "+f"((d)[2]), "+f"((d)[3]) \
    : "r"((a)[0]), "r"((a)[1]), "r"((a)[2]), "r"((a)[3]), "r"((b)[0]), "r"((b)[1]))

// 128 rows x 64B tile; row pairs packed into 128B lines, xor swizzle.
__device__ __forceinline__ uint32_t tile_addr(uint32_t base, int row, int cb) {
    uint32_t off = ((uint32_t)(row >> 1) << 7) + ((uint32_t)(row & 1) << 6) + (uint32_t)cb;
    return base + (off ^ (((uint32_t)(row >> 1) & 7u) << 4));
}
__device__ __forceinline__ void split2h(float v, __half& h, __half& l) {
    h = __float2half(v);
    l = __float2half(v - __half2float(h));
}

// ---------------------------------------------------------------------------
// coeff kernel
// ---------------------------------------------------------------------------
__global__ __launch_bounds__(256) void coeff_kernel(
    const float* __restrict__ x, const float* __restrict__ Wu,
    const float* __restrict__ bu)
{
    int t = blockIdx.x * 8 + (threadIdx.x >> 5);
    int lane = threadIdx.x & 31;
    if (t >= M_TOK) return;
    const float4* xr = (const float4*)(x + (size_t)t * DD);
    const float4* wr = (const float4*)Wu;
    float sum = 0.f;
#pragma unroll
    for (int i = lane; i < DD / 4; i += 32) {
        float4 a = xr[i], b = wr[i];
        sum += a.x * b.x + a.y * b.y + a.z * b.z + a.w * b.w;
    }
#pragma unroll
    for (int o = 16; o; o >>= 1) sum += __shfl_xor_sync(0xffffffffu, sum, o);
    if (lane == 0) {
        float z = sum + bu[0];
        float u = 1.f / (1.f + expf(-z));
        int k = (int)ceilf(u * (float)EE);
        k = k < 1 ? 1 : (k > EE ? EE : k);
        int s = t & SMASK;
#pragma unroll
        for (int e = 0; e < EE; e++) {
            int ie = ((e - s) & 3) + 1;
            g_c[t * EE + e] = (k >= ie) ? (u / (float)ie) : 0.f;
        }
    }
}

__global__ void init_cnt_kernel() {
    if (threadIdx.x < EE) g_cnt[threadIdx.x] = 0;
}

__global__ __launch_bounds__(256) void build_lists_kernel() {
    int t = blockIdx.x * 256 + threadIdx.x;
    if (t >= M_TOK) return;
#pragma unroll
    for (int e = 0; e < EE; e++) {
        if (g_c[t * EE + e] != 0.f) {
            int p = atomicAdd(&g_cnt[e], 1);
            g_list[e * M_TOK + p] = t;
            g_pos[t * EE + e] = p;
        }
    }
}

// ---------------------------------------------------------------------------
// fp32 -> fp16 hi/lo split (x activations)
// ---------------------------------------------------------------------------
__global__ __launch_bounds__(256) void convert_split_kernel(
    const float* __restrict__ in, __half* __restrict__ oh,
    __half* __restrict__ ol)
{
    size_t i = ((size_t)blockIdx.x * 256 + threadIdx.x) * 4;
    float4 v = *(const float4*)(in + i);
    float vv[4] = {v.x, v.y, v.z, v.w};
    __half h[4], l[4];
#pragma unroll
    for (int j = 0; j < 4; j++) split2h(vv[j], h[j], l[j]);
    *(__half2*)(oh + i)     = __half2(h[0], h[1]);
    *(__half2*)(oh + i + 2) = __half2(h[2], h[3]);
    *(__half2*)(ol + i)     = __half2(l[0], l[1]);
    *(__half2*)(ol + i + 2) = __half2(l[2], l[3]);
}

// ---------------------------------------------------------------------------
// transpose [R,C] -> [C,R], fp16 single (weights); blockIdx.z batches
// ---------------------------------------------------------------------------
__global__ __launch_bounds__(256) void transpose_h_kernel(
    const float* __restrict__ in, __half* __restrict__ o, int R, int C)
{
    __shared__ float tile[32][33];
    size_t zoff = (size_t)blockIdx.z * R * C;
    int c0 = blockIdx.x * 32, r0 = blockIdx.y * 32;
    int tx = threadIdx.x, ty = threadIdx.y;
#pragma unroll
    for (int j = 0; j < 32; j += 8)
        tile[ty + j][tx] = in[zoff + (size_t)(r0 + ty + j) * C + c0 + tx];
    __syncthreads();
#pragma unroll
    for (int j = 0; j < 32; j += 8) {
        size_t off = zoff + (size_t)(c0 + ty + j) * R + r0 + tx;
        o[off] = __float2half(tile[tx][ty + j]);
    }
}

// ---------------------------------------------------------------------------
// sparse per-expert fp16 GEMM, 128x128 tile, BK=32, 2-term split (Ah,Al)xB,
// 4-stage cp.async. Stage = {Ah:0, Al:8192, B:16384} = 24576B.
// MODE1: A = x gathered via g_list[e], B = W1T_e, epilogue relu(acc+b1)*c ->
//        fp16 hi/lo H_e.    grid (Mtile=64, Ntile=32, e)
// MODE2: A = H_e compacted, B = W2T_e, C = y_e fp32.  grid (8, Mtile, e)
// ---------------------------------------------------------------------------
template <int MODE>
__global__ __launch_bounds__(256, 1) void gemm_kernel(
    const __half* __restrict__ Ah, const __half* __restrict__ Al,
    const __half* __restrict__ Bf,
    const float* __restrict__ bias,
    __half* __restrict__ Ch, __half* __restrict__ Cl,
    float* __restrict__ Yo)
{
    const int KTOT = (MODE == 1) ? DD : FF;
    const int NK   = KTOT / 32;
    const uint32_t STAGE = 24576u;

    extern __shared__ char smem[];
    uint32_t sbase = smem_u32(smem);
    int* sList = (int*)(smem + 4 * STAGE);

    const int tid = threadIdx.x;
    const int lane = tid & 31;
    const int wid = tid >> 5;
    const int wm = wid >> 2;
    const int wn = wid & 3;

    const int e = blockIdx.z;
    const int n_e = g_cnt[e];
    const int mtiles = (n_e + 127) >> 7;
    const int mt = (MODE == 1) ? blockIdx.x : blockIdx.y;
    if (mt >= mtiles) return;
    const int bm = mt * 128;
    const int bn = ((MODE == 1) ? blockIdx.y : blockIdx.x) * 128;

    if (MODE == 1) {
        if (tid < 128) {
            int idx = bm + tid;
            sList[tid] = (idx < n_e) ? g_list[e * M_TOK + idx] : 0;
        }
        __syncthreads();
    }

    auto load_chunk = [&](int k0, int slot) {
        uint32_t base = sbase + (uint32_t)slot * STAGE;
#pragma unroll
        for (int q = 0; q < 6; q++) {
            int lin = tid + q * 256;          // 0..1535
            int tl  = lin >> 9;               // 0..2
            int r   = (lin >> 2) & 127;
            int cq  = lin & 3;
            int cb  = cq * 16;
            int ke  = k0 + cq * 8;
            const __half* src;
            if (MODE == 1) {
                if      (tl == 0) src = Ah + (size_t)sList[r] * DD + ke;
                else if (tl == 1) src = Al + (size_t)sList[r] * DD + ke;
                else              src = Bf + ((size_t)e * FF + bn + r) * DD + ke;
            } else {
                if      (tl == 0) src = Ah + (size_t)e * M_TOK * FF + (size_t)(bm + r) * FF + ke;
                else if (tl == 1) src = Al + (size_t)e * M_TOK * FF + (size_t)(bm + r) * FF + ke;
                else              src = Bf + (size_t)(bn + r) * N1 + e * FF + ke;
            }
            CP16(tile_addr(base + (uint32_t)tl * 8192u, r, cb), src);
        }
        CP_COMMIT();
    };

    float acc[4][4][4];
#pragma unroll
    for (int mi = 0; mi < 4; mi++)
#pragma unroll
        for (int ni = 0; ni < 4; ni++)
#pragma unroll
            for (int j = 0; j < 4; j++) acc[mi][ni][j] = 0.f;

    load_chunk(0, 0);
    load_chunk(32, 1);
    load_chunk(64, 2);

    const int a_row = (lane & 15);
    const int a_cbo = ((lane >> 4) & 1) * 16;
    const int bll   = lane & 15;
    const int b_row = (bll & 7);
    const int b_cbo = ((bll >> 3) & 1) * 16;

    for (int i = 0; i < NK; i++) {
        CP_WAIT(2);
        __syncthreads();
        if (i + 3 < NK) load_chunk((i + 3) * 32, (i + 3) & 3);

        uint32_t base = sbase + (uint32_t)(i & 3) * STAGE;
        uint32_t bAh = base, bAl = base + 8192u, bB = base + 16384u;

#pragma unroll
        for (int ks = 0; ks < 2; ks++) {
            int kb = ks * 32;
            uint32_t ah[4][4], al[4][4], bb[4][2];
#pragma unroll
            for (int mi = 0; mi < 4; mi++) {
                int r = wm * 64 + mi * 16 + a_row;
                LDMX4(ah[mi], tile_addr(bAh, r, kb + a_cbo));
                LDMX4(al[mi], tile_addr(bAl, r, kb + a_cbo));
            }
#pragma unroll
            for (int ni = 0; ni < 4; ni++) {
                int r = wn * 32 + ni * 8 + b_row;
                LDMX2(bb[ni], tile_addr(bB, r, kb + b_cbo));
            }
#pragma unroll
            for (int mi = 0; mi < 4; mi++)
#pragma unroll
                for (int ni = 0; ni < 4; ni++) MMA16816(acc[mi][ni], ah[mi], bb[ni]);
#pragma unroll
            for (int mi = 0; mi < 4; mi++)
#pragma unroll
                for (int ni = 0; ni < 4; ni++) MMA16816(acc[mi][ni], al[mi], bb[ni]);
        }
    }
    CP_WAIT(0);
    __syncthreads();

    // acc(mi,ni,j): row = wm*64+mi*16+(lane>>2)+(j>>1)*8, col = wn*32+ni*8+(lane&3)*2+(j&1)
    if (MODE == 1) {
        float bv[4][2];
#pragma unroll
        for (int ni = 0; ni < 4; ni++) {
            int c0 = wn * 32 + ni * 8 + (lane & 3) * 2;
            bv[ni][0] = bias[(size_t)e * FF + bn + c0];
            bv[ni][1] = bias[(size_t)e * FF + bn + c0 + 1];
        }
#pragma unroll
        for (int mi = 0; mi < 4; mi++)
#pragma unroll
            for (int h = 0; h < 2; h++) {
                int row = wm * 64 + mi * 16 + (lane >> 2) + h * 8;
                float cv = (bm + row < n_e) ? g_c[sList[row] * EE + e] : 0.f;
#pragma unroll
                for (int ni = 0; ni < 4; ni++) {
                    int c0 = wn * 32 + ni * 8 + (lane & 3) * 2;
                    float v0 = fmaxf(acc[mi][ni][h * 2 + 0] + bv[ni][0], 0.f) * cv;
                    float v1 = fmaxf(acc[mi][ni][h * 2 + 1] + bv[ni][1], 0.f) * cv;
                    __half h0, l0, h1, l1;
                    split2h(v0, h0, l0);
                    split2h(v1, h1, l1);
                    *(__half2*)(smem + row * 256 + c0 * 2)         = __half2(h0, h1);
                    *(__half2*)(smem + 32768 + row * 256 + c0 * 2) = __half2(l0, l1);
                }
            }
        __syncthreads();
#pragma unroll
        for (int q = 0; q < 16; q++) {
            int lin = tid + q * 256;
            int mat = lin >> 11;
            int l2  = lin & 2047;
            int r   = l2 >> 4;
            int cw  = l2 & 15;
            uint4 v = *(uint4*)(smem + mat * 32768 + r * 256 + cw * 16);
            __half* dst = (mat == 0 ? Ch : Cl);
            *(uint4*)(dst + (size_t)e * M_TOK * FF + (size_t)(bm + r) * FF + bn + cw * 8) = v;
        }
    } else {
#pragma unroll
        for (int mi = 0; mi < 4; mi++)
#pragma unroll
            for (int h = 0; h < 2; h++) {
                int row = wm * 64 + mi * 16 + (lane >> 2) + h * 8;
#pragma unroll
                for (int ni = 0; ni < 4; ni++) {
                    int c0 = wn * 32 + ni * 8 + (lane & 3) * 2;
                    *(float*)(smem + row * 512 + c0 * 4)       = acc[mi][ni][h * 2 + 0];
                    *(float*)(smem + row * 512 + (c0 + 1) * 4) = acc[mi][ni][h * 2 + 1];
                }
            }
        __syncthreads();
#pragma unroll
        for (int q = 0; q < 16; q++) {
            int lin = tid + q * 256;
            int r   = lin >> 5;
            int cw  = lin & 31;
            uint4 v = *(uint4*)(smem + r * 512 + cw * 16);
            *(uint4*)(Yo + (size_t)e * M_TOK * DD + (size_t)(bm + r) * DD + bn + cw * 4) = v;
        }
    }
}

// ---------------------------------------------------------------------------
// final gather: out[t] = sum over active e of (y_e[pos] + c_e*b2_e)
// ---------------------------------------------------------------------------
__global__ __launch_bounds__(256) void gather_out_kernel(
    const float* __restrict__ y, const float* __restrict__ b2,
    float* __restrict__ out)
{
    int t = blockIdx.x;
    int d = threadIdx.x * 4;
    float acc0 = 0.f, acc1 = 0.f, acc2 = 0.f, acc3 = 0.f;
#pragma unroll
    for (int e = 0; e < EE; e++) {
        float c = g_c[t * EE + e];
        if (c != 0.f) {
            int pos = g_pos[t * EE + e];
            float4 vy = *(const float4*)(y + (size_t)e * M_TOK * DD + (size_t)pos * DD + d);
            float4 vb = *(const float4*)(b2 + e * DD + d);
            acc0 += vy.x + c * vb.x;
            acc1 += vy.y + c * vb.y;
            acc2 += vy.z + c * vb.z;
            acc3 += vy.w + c * vb.w;
        }
    }
    float4 o = {acc0, acc1, acc2, acc3};
    *(float4*)(out + (size_t)t * DD + d) = o;
}

// ---------------------------------------------------------------------------
// launch. Inputs: x, W1, b1, W2, b2, Wu, bu
// ---------------------------------------------------------------------------
extern "C" void kernel_launch(void* const* d_in, const int* in_sizes, int n_in,
                              void* d_out, int out_size)
{
    const float* x  = (const float*)d_in[0];
    const float* W1 = (const float*)d_in[1];
    const float* b1 = (const float*)d_in[2];
    const float* W2 = (const float*)d_in[3];
    const float* b2 = (const float*)d_in[4];
    const float* Wu = (const float*)d_in[5];
    const float* bu = (const float*)d_in[6];
    float* out = (float*)d_out;
    (void)in_sizes; (void)n_in; (void)out_size;

    __half *xh, *xl, *w1, *w2, *Hh, *Hl;
    float* y;
    cudaGetSymbolAddress((void**)&xh, g_xh);
    cudaGetSymbolAddress((void**)&xl, g_xl);
    cudaGetSymbolAddress((void**)&w1, g_w1);
    cudaGetSymbolAddress((void**)&w2, g_w2);
    cudaGetSymbolAddress((void**)&Hh, g_Hh);
    cudaGetSymbolAddress((void**)&Hl, g_Hl);
    cudaGetSymbolAddress((void**)&y,  g_y);

    const int SMEM_GEMM = 4 * 24576 + 512;  // 98816
    cudaFuncSetAttribute(gemm_kernel<1>,
                         cudaFuncAttributeMaxDynamicSharedMemorySize, SMEM_GEMM);
    cudaFuncSetAttribute(gemm_kernel<2>,
                         cudaFuncAttributeMaxDynamicSharedMemorySize, SMEM_GEMM);

    coeff_kernel<<<M_TOK / 8, 256>>>(x, Wu, bu);
    init_cnt_kernel<<<1, 32>>>();
    build_lists_kernel<<<M_TOK / 256, 256>>>();

    convert_split_kernel<<<(M_TOK * DD) / (256 * 4), 256>>>(x, xh, xl);
    {   // W1 [E][D,F] -> [E*F, D] fp16
        dim3 grid(FF / 32, DD / 32, EE);
        transpose_h_kernel<<<grid, dim3(32, 8)>>>(W1, w1, DD, FF);
    }
    {   // W2 [E*F, D] -> [D, E*F] fp16
        dim3 grid(DD / 32, N1 / 32, 1);
        transpose_h_kernel<<<grid, dim3(32, 8)>>>(W2, w2, N1, DD);
    }

    {   // GEMM1 sparse: per-expert [n_e,1024] x [1024,4096] -> H_e fp16 hi/lo
        dim3 grid(M_TOK / 128, FF / 128, EE);   // Mtile fast (B-panel reuse)
        gemm_kernel<1><<<grid, 256, SMEM_GEMM>>>(
            xh, xl, w1, b1, Hh, Hl, nullptr);
    }
    {   // GEMM2 sparse: per-expert [n_e,4096] x [4096,1024] -> y_e fp32
        dim3 grid(DD / 128, M_TOK / 128, EE);   // Ntile fast (A-panel reuse)
        gemm_kernel<2><<<grid, 256, SMEM_GEMM>>>(
            Hh, Hl, w2, nullptr, nullptr, nullptr, y);
    }

    gather_out_kernel<<<M_TOK, 256>>>(y, b2, out);
}

// round 7
// speedup vs baseline: 9.5755x; 1.5178x over previous
#include <cuda_runtime.h>
#include <cuda_fp16.h>
#include <math.h>
#include <stdint.h>

// ---------------- problem constants ----------------
#define M_TOK 8192
#define DD    1024
#define FF    4096
#define EE    4
#define N1    16384
#define SMASK 2047

// ---------------- scratch (__device__ globals; no allocs allowed) ----------
__device__ float   g_c [M_TOK * EE];
__device__ int     g_cnt[EE];
__device__ int     g_list[EE * M_TOK];
__device__ int     g_pos[M_TOK * EE];
__device__ __half  g_x [(size_t)M_TOK * DD];        // x fp16
__device__ __half  g_w1[(size_t)N1 * DD];           // W1T fp16
__device__ __half  g_w2[(size_t)DD * N1];           // W2T fp16
__device__ __half  g_H [(size_t)EE * M_TOK * FF];   // per-expert compacted H fp16
__device__ float   g_y [(size_t)EE * M_TOK * DD];   // per-expert compacted fp32

// ---------------- helpers ----------------
__device__ __forceinline__ uint32_t smem_u32(const void* p) {
    uint32_t a;
    asm("{ .reg .u64 t; cvta.to.shared.u64 t, %1; cvt.u32.u64 %0, t; }" : "=r"(a) : "l"(p));
    return a;
}
#define CP16(sm, g)   asm volatile("cp.async.cg.shared.global [%0], [%1], 16;" :: "r"(sm), "l"(g) : "memory")
#define CP_COMMIT()   asm volatile("cp.async.commit_group;" ::: "memory")
#define CP_WAIT(n)    asm volatile("cp.async.wait_group %0;" :: "n"(n) : "memory")

#define LDMX4(r, a) asm volatile( \
    "ldmatrix.sync.aligned.m8n8.x4.shared.b16 {%0,%1,%2,%3}, [%4];" \
    : "=r"((r)[0]), "=r"((r)[1]), "=r"((r)[2]), "=r"((r)[3]) : "r"(a))
#define LDMX2(r, a) asm volatile( \
    "ldmatrix.sync.aligned.m8n8.x2.shared.b16 {%0,%1}, [%2];" \
    : "=r"((r)[0]), "=r"((r)[1]) : "r"(a))
#define MMA16816(d, a, b) asm volatile( \
    "mma.sync.aligned.m16n8k16.row.col.f32.f16.f16.f32 " \
    "{%0,%1,%2,%3}, {%4,%5,%6,%7}, {%8,%9}, {%0,%1,%2,%3};" \
    : "+f"((d)[0]), "+f"((d)[1]), "+f"((d)[2]), "+f"((d)[3]) \
    : "r"((a)[0]), "r"((a)[1]), "r"((a)[2]), "r"((a)[3]), "r"((b)[0]), "r"((b)[1]))

// 128 rows x 64B tile; row pairs packed into 128B lines, xor swizzle.
__device__ __forceinline__ uint32_t tile_addr(uint32_t base, int row, int cb) {
    uint32_t off = ((uint32_t)(row >> 1) << 7) + ((uint32_t)(row & 1) << 6) + (uint32_t)cb;
    return base + (off ^ (((uint32_t)(row >> 1) & 7u) << 4));
}

// ---------------------------------------------------------------------------
// coeff kernel (fp32 exact — keeps discrete k decision bit-stable)
// ---------------------------------------------------------------------------
__global__ __launch_bounds__(256) void coeff_kernel(
    const float* __restrict__ x, const float* __restrict__ Wu,
    const float* __restrict__ bu)
{
    int t = blockIdx.x * 8 + (threadIdx.x >> 5);
    int lane = threadIdx.x & 31;
    if (t >= M_TOK) return;
    const float4* xr = (const float4*)(x + (size_t)t * DD);
    const float4* wr = (const float4*)Wu;
    float sum = 0.f;
#pragma unroll
    for (int i = lane; i < DD / 4; i += 32) {
        float4 a = xr[i], b = wr[i];
        sum += a.x * b.x + a.y * b.y + a.z * b.z + a.w * b.w;
    }
#pragma unroll
    for (int o = 16; o; o >>= 1) sum += __shfl_xor_sync(0xffffffffu, sum, o);
    if (lane == 0) {
        float z = sum + bu[0];
        float u = 1.f / (1.f + expf(-z));
        int k = (int)ceilf(u * (float)EE);
        k = k < 1 ? 1 : (k > EE ? EE : k);
        int s = t & SMASK;
#pragma unroll
        for (int e = 0; e < EE; e++) {
            int ie = ((e - s) & 3) + 1;
            g_c[t * EE + e] = (k >= ie) ? (u / (float)ie) : 0.f;
        }
    }
}

__global__ void init_cnt_kernel() {
    if (threadIdx.x < EE) g_cnt[threadIdx.x] = 0;
}

__global__ __launch_bounds__(256) void build_lists_kernel() {
    int t = blockIdx.x * 256 + threadIdx.x;
    if (t >= M_TOK) return;
#pragma unroll
    for (int e = 0; e < EE; e++) {
        if (g_c[t * EE + e] != 0.f) {
            int p = atomicAdd(&g_cnt[e], 1);
            g_list[e * M_TOK + p] = t;
            g_pos[t * EE + e] = p;
        }
    }
}

// ---------------------------------------------------------------------------
// fp32 -> fp16 (x)
// ---------------------------------------------------------------------------
__global__ __launch_bounds__(256) void convert_h_kernel(
    const float* __restrict__ in, __half* __restrict__ o)
{
    size_t i = ((size_t)blockIdx.x * 256 + threadIdx.x) * 4;
    float4 v = *(const float4*)(in + i);
    *(__half2*)(o + i)     = __half2(__float2half(v.x), __float2half(v.y));
    *(__half2*)(o + i + 2) = __half2(__float2half(v.z), __float2half(v.w));
}

// ---------------------------------------------------------------------------
// transpose [R,C] -> [C,R] fp16; blockIdx.z batches
// ---------------------------------------------------------------------------
__global__ __launch_bounds__(256) void transpose_h_kernel(
    const float* __restrict__ in, __half* __restrict__ o, int R, int C)
{
    __shared__ float tile[32][33];
    size_t zoff = (size_t)blockIdx.z * R * C;
    int c0 = blockIdx.x * 32, r0 = blockIdx.y * 32;
    int tx = threadIdx.x, ty = threadIdx.y;
#pragma unroll
    for (int j = 0; j < 32; j += 8)
        tile[ty + j][tx] = in[zoff + (size_t)(r0 + ty + j) * C + c0 + tx];
    __syncthreads();
#pragma unroll
    for (int j = 0; j < 32; j += 8) {
        size_t off = zoff + (size_t)(c0 + ty + j) * R + r0 + tx;
        o[off] = __float2half(tile[tx][ty + j]);
    }
}

// ---------------------------------------------------------------------------
// sparse per-expert fp16 GEMM, 128x128 tile, BK=32, single term, 4-stage
// cp.async. Stage = {A:0, B:8192} = 16384B.
// MODE1: A = x gathered via g_list[e], B = W1T_e, epilogue relu(acc+b1)*c ->
//        H_e fp16.        grid (Mtile=64, Ntile=32, e)
// MODE2: A = H_e compacted, B = W2T_e, C = y_e fp32.  grid (8, Mtile, e)
// ---------------------------------------------------------------------------
template <int MODE>
__global__ __launch_bounds__(256, 1) void gemm_kernel(
    const __half* __restrict__ Af, const __half* __restrict__ Bf,
    const float* __restrict__ bias,
    __half* __restrict__ Ch, float* __restrict__ Yo)
{
    const int KTOT = (MODE == 1) ? DD : FF;
    const int NK   = KTOT / 32;
    const uint32_t STAGE = 16384u;

    extern __shared__ char smem[];
    uint32_t sbase = smem_u32(smem);
    int* sList = (int*)(smem + 4 * STAGE);

    const int tid = threadIdx.x;
    const int lane = tid & 31;
    const int wid = tid >> 5;
    const int wm = wid >> 2;
    const int wn = wid & 3;

    const int e = blockIdx.z;
    const int n_e = g_cnt[e];
    const int mtiles = (n_e + 127) >> 7;
    const int mt = (MODE == 1) ? blockIdx.x : blockIdx.y;
    if (mt >= mtiles) return;
    const int bm = mt * 128;
    const int bn = ((MODE == 1) ? blockIdx.y : blockIdx.x) * 128;

    if (MODE == 1) {
        if (tid < 128) {
            int idx = bm + tid;
            sList[tid] = (idx < n_e) ? g_list[e * M_TOK + idx] : 0;
        }
        __syncthreads();
    }

    auto load_chunk = [&](int k0, int slot) {
        uint32_t base = sbase + (uint32_t)slot * STAGE;
#pragma unroll
        for (int q = 0; q < 4; q++) {
            int lin = tid + q * 256;          // 0..1023
            int tl  = lin >> 9;               // 0..1 (A, B)
            int r   = (lin >> 2) & 127;
            int cq  = lin & 3;
            int cb  = cq * 16;
            int ke  = k0 + cq * 8;
            const __half* src;
            if (MODE == 1) {
                if (tl == 0) src = Af + (size_t)sList[r] * DD + ke;
                else         src = Bf + ((size_t)e * FF + bn + r) * DD + ke;
            } else {
                if (tl == 0) src = Af + (size_t)e * M_TOK * FF + (size_t)(bm + r) * FF + ke;
                else         src = Bf + (size_t)(bn + r) * N1 + e * FF + ke;
            }
            CP16(tile_addr(base + (uint32_t)tl * 8192u, r, cb), src);
        }
        CP_COMMIT();
    };

    float acc[4][4][4];
#pragma unroll
    for (int mi = 0; mi < 4; mi++)
#pragma unroll
        for (int ni = 0; ni < 4; ni++)
#pragma unroll
            for (int j = 0; j < 4; j++) acc[mi][ni][j] = 0.f;

    load_chunk(0, 0);
    load_chunk(32, 1);
    load_chunk(64, 2);

    const int a_row = (lane & 15);
    const int a_cbo = ((lane >> 4) & 1) * 16;
    const int bll   = lane & 15;
    const int b_row = (bll & 7);
    const int b_cbo = ((bll >> 3) & 1) * 16;

    for (int i = 0; i < NK; i++) {
        CP_WAIT(2);
        __syncthreads();
        if (i + 3 < NK) load_chunk((i + 3) * 32, (i + 3) & 3);

        uint32_t base = sbase + (uint32_t)(i & 3) * STAGE;
        uint32_t bA = base, bB = base + 8192u;

#pragma unroll
        for (int ks = 0; ks < 2; ks++) {
            int kb = ks * 32;
            uint32_t aa[4][4], bb[4][2];
#pragma unroll
            for (int mi = 0; mi < 4; mi++) {
                int r = wm * 64 + mi * 16 + a_row;
                LDMX4(aa[mi], tile_addr(bA, r, kb + a_cbo));
            }
#pragma unroll
            for (int ni = 0; ni < 4; ni++) {
                int r = wn * 32 + ni * 8 + b_row;
                LDMX2(bb[ni], tile_addr(bB, r, kb + b_cbo));
            }
#pragma unroll
            for (int mi = 0; mi < 4; mi++)
#pragma unroll
                for (int ni = 0; ni < 4; ni++) MMA16816(acc[mi][ni], aa[mi], bb[ni]);
        }
    }
    CP_WAIT(0);
    __syncthreads();

    // acc(mi,ni,j): row = wm*64+mi*16+(lane>>2)+(j>>1)*8, col = wn*32+ni*8+(lane&3)*2+(j&1)
    if (MODE == 1) {
        float bv[4][2];
#pragma unroll
        for (int ni = 0; ni < 4; ni++) {
            int c0 = wn * 32 + ni * 8 + (lane & 3) * 2;
            bv[ni][0] = bias[(size_t)e * FF + bn + c0];
            bv[ni][1] = bias[(size_t)e * FF + bn + c0 + 1];
        }
#pragma unroll
        for (int mi = 0; mi < 4; mi++)
#pragma unroll
            for (int h = 0; h < 2; h++) {
                int row = wm * 64 + mi * 16 + (lane >> 2) + h * 8;
                float cv = (bm + row < n_e) ? g_c[sList[row] * EE + e] : 0.f;
#pragma unroll
                for (int ni = 0; ni < 4; ni++) {
                    int c0 = wn * 32 + ni * 8 + (lane & 3) * 2;
                    float v0 = fmaxf(acc[mi][ni][h * 2 + 0] + bv[ni][0], 0.f) * cv;
                    float v1 = fmaxf(acc[mi][ni][h * 2 + 1] + bv[ni][1], 0.f) * cv;
                    *(__half2*)(smem + row * 256 + c0 * 2) =
                        __half2(__float2half(v0), __float2half(v1));
                }
            }
        __syncthreads();
#pragma unroll
        for (int q = 0; q < 8; q++) {
            int lin = tid + q * 256;          // 0..2047
            int r   = lin >> 4;
            int cw  = lin & 15;
            uint4 v = *(uint4*)(smem + r * 256 + cw * 16);
            *(uint4*)(Ch + (size_t)e * M_TOK * FF + (size_t)(bm + r) * FF + bn + cw * 8) = v;
        }
    } else {
#pragma unroll
        for (int mi = 0; mi < 4; mi++)
#pragma unroll
            for (int h = 0; h < 2; h++) {
                int row = wm * 64 + mi * 16 + (lane >> 2) + h * 8;
#pragma unroll
                for (int ni = 0; ni < 4; ni++) {
                    int c0 = wn * 32 + ni * 8 + (lane & 3) * 2;
                    *(float*)(smem + row * 512 + c0 * 4)       = acc[mi][ni][h * 2 + 0];
                    *(float*)(smem + row * 512 + (c0 + 1) * 4) = acc[mi][ni][h * 2 + 1];
                }
            }
        __syncthreads();
#pragma unroll
        for (int q = 0; q < 16; q++) {
            int lin = tid + q * 256;
            int r   = lin >> 5;
            int cw  = lin & 31;
            uint4 v = *(uint4*)(smem + r * 512 + cw * 16);
            *(uint4*)(Yo + (size_t)e * M_TOK * DD + (size_t)(bm + r) * DD + bn + cw * 4) = v;
        }
    }
}

// ---------------------------------------------------------------------------
// final gather: out[t] = sum over active e of (y_e[pos] + c_e*b2_e)
// ---------------------------------------------------------------------------
__global__ __launch_bounds__(256) void gather_out_kernel(
    const float* __restrict__ y, const float* __restrict__ b2,
    float* __restrict__ out)
{
    int t = blockIdx.x;
    int d = threadIdx.x * 4;
    float acc0 = 0.f, acc1 = 0.f, acc2 = 0.f, acc3 = 0.f;
#pragma unroll
    for (int e = 0; e < EE; e++) {
        float c = g_c[t * EE + e];
        if (c != 0.f) {
            int pos = g_pos[t * EE + e];
            float4 vy = *(const float4*)(y + (size_t)e * M_TOK * DD + (size_t)pos * DD + d);
            float4 vb = *(const float4*)(b2 + e * DD + d);
            acc0 += vy.x + c * vb.x;
            acc1 += vy.y + c * vb.y;
            acc2 += vy.z + c * vb.z;
            acc3 += vy.w + c * vb.w;
        }
    }
    float4 o = {acc0, acc1, acc2, acc3};
    *(float4*)(out + (size_t)t * DD + d) = o;
}

// ---------------------------------------------------------------------------
// launch. Inputs: x, W1, b1, W2, b2, Wu, bu
// ---------------------------------------------------------------------------
extern "C" void kernel_launch(void* const* d_in, const int* in_sizes, int n_in,
                              void* d_out, int out_size)
{
    const float* x  = (const float*)d_in[0];
    const float* W1 = (const float*)d_in[1];
    const float* b1 = (const float*)d_in[2];
    const float* W2 = (const float*)d_in[3];
    const float* b2 = (const float*)d_in[4];
    const float* Wu = (const float*)d_in[5];
    const float* bu = (const float*)d_in[6];
    float* out = (float*)d_out;
    (void)in_sizes; (void)n_in; (void)out_size;

    __half *xf, *w1, *w2, *H;
    float* y;
    cudaGetSymbolAddress((void**)&xf, g_x);
    cudaGetSymbolAddress((void**)&w1, g_w1);
    cudaGetSymbolAddress((void**)&w2, g_w2);
    cudaGetSymbolAddress((void**)&H,  g_H);
    cudaGetSymbolAddress((void**)&y,  g_y);

    const int SMEM_GEMM = 4 * 16384 + 512;  // 66048
    cudaFuncSetAttribute(gemm_kernel<1>,
                         cudaFuncAttributeMaxDynamicSharedMemorySize, SMEM_GEMM);
    cudaFuncSetAttribute(gemm_kernel<2>,
                         cudaFuncAttributeMaxDynamicSharedMemorySize, SMEM_GEMM);

    coeff_kernel<<<M_TOK / 8, 256>>>(x, Wu, bu);
    init_cnt_kernel<<<1, 32>>>();
    build_lists_kernel<<<M_TOK / 256, 256>>>();

    convert_h_kernel<<<(M_TOK * DD) / (256 * 4), 256>>>(x, xf);
    {   // W1 [E][D,F] -> [E*F, D] fp16
        dim3 grid(FF / 32, DD / 32, EE);
        transpose_h_kernel<<<grid, dim3(32, 8)>>>(W1, w1, DD, FF);
    }
    {   // W2 [E*F, D] -> [D, E*F] fp16
        dim3 grid(DD / 32, N1 / 32, 1);
        transpose_h_kernel<<<grid, dim3(32, 8)>>>(W2, w2, N1, DD);
    }

    {   // GEMM1 sparse: per-expert [n_e,1024] x [1024,4096] -> H_e fp16
        dim3 grid(M_TOK / 128, FF / 128, EE);   // Mtile fast (B-panel reuse)
        gemm_kernel<1><<<grid, 256, SMEM_GEMM>>>(xf, w1, b1, H, nullptr);
    }
    {   // GEMM2 sparse: per-expert [n_e,4096] x [4096,1024] -> y_e fp32
        dim3 grid(DD / 128, M_TOK / 128, EE);   // Ntile fast (A-panel reuse)
        gemm_kernel<2><<<grid, 256, SMEM_GEMM>>>(H, w2, nullptr, nullptr, y);
    }

    gather_out_kernel<<<M_TOK, 256>>>(y, b2, out);
}

// round 8
// speedup vs baseline: 11.0499x; 1.1540x over previous
#include <cuda_runtime.h>
#include <cuda_fp16.h>
#include <math.h>
#include <stdint.h>

// ---------------- problem constants ----------------
#define M_TOK 8192
#define DD    1024
#define FF    4096
#define EE    4
#define N1    16384
#define SMASK 2047

// ---------------- scratch (__device__ globals; no allocs allowed) ----------
__device__ float   g_c [M_TOK * EE];
__device__ int     g_cnt[EE];
__device__ int     g_list[EE * M_TOK];
__device__ int     g_pos[M_TOK * EE];
__device__ __half  g_x [(size_t)M_TOK * DD];
__device__ __half  g_w1[(size_t)N1 * DD];
__device__ __half  g_w2[(size_t)DD * N1];
__device__ __half  g_H [(size_t)EE * M_TOK * FF];
__device__ float   g_y [(size_t)EE * M_TOK * DD];

// ---------------- helpers ----------------
__device__ __forceinline__ uint32_t smem_u32(const void* p) {
    uint32_t a;
    asm("{ .reg .u64 t; cvta.to.shared.u64 t, %1; cvt.u32.u64 %0, t; }" : "=r"(a) : "l"(p));
    return a;
}
#define CP16(sm, g)   asm volatile("cp.async.cg.shared.global [%0], [%1], 16;" :: "r"(sm), "l"(g) : "memory")
#define CP_COMMIT()   asm volatile("cp.async.commit_group;" ::: "memory")
#define CP_WAIT(n)    asm volatile("cp.async.wait_group %0;" :: "n"(n) : "memory")

#define LDMX4(r, a) asm volatile( \
    "ldmatrix.sync.aligned.m8n8.x4.shared.b16 {%0,%1,%2,%3}, [%4];" \
    : "=r"((r)[0]), "=r"((r)[1]), "=r"((r)[2]), "=r"((r)[3]) : "r"(a))
#define MMA16816(d, a, b) asm volatile( \
    "mma.sync.aligned.m16n8k16.row.col.f32.f16.f16.f32 " \
    "{%0,%1,%2,%3}, {%4,%5,%6,%7}, {%8,%9}, {%0,%1,%2,%3};" \
    : "+f"((d)[0]), "+f"((d)[1]), "+f"((d)[2]), "+f"((d)[3]) \
    : "r"((a)[0]), "r"((a)[1]), "r"((a)[2]), "r"((a)[3]), "r"((b)[0]), "r"((b)[1]))

// 128 rows x 64B tile block; row pairs packed into 128B lines, xor swizzle.
__device__ __forceinline__ uint32_t tile_addr(uint32_t base, int row, int cb) {
    uint32_t off = ((uint32_t)(row >> 1) << 7) + ((uint32_t)(row & 1) << 6) + (uint32_t)cb;
    return base + (off ^ (((uint32_t)(row >> 1) & 7u) << 4));
}

// ---------------------------------------------------------------------------
// coeff + list build fused (g_cnt must be zeroed first)
// ---------------------------------------------------------------------------
__global__ __launch_bounds__(256) void coeff_kernel(
    const float* __restrict__ x, const float* __restrict__ Wu,
    const float* __restrict__ bu)
{
    int t = blockIdx.x * 8 + (threadIdx.x >> 5);
    int lane = threadIdx.x & 31;
    if (t >= M_TOK) return;
    const float4* xr = (const float4*)(x + (size_t)t * DD);
    const float4* wr = (const float4*)Wu;
    float sum = 0.f;
#pragma unroll
    for (int i = lane; i < DD / 4; i += 32) {
        float4 a = xr[i], b = wr[i];
        sum += a.x * b.x + a.y * b.y + a.z * b.z + a.w * b.w;
    }
#pragma unroll
    for (int o = 16; o; o >>= 1) sum += __shfl_xor_sync(0xffffffffu, sum, o);
    if (lane == 0) {
        float z = sum + bu[0];
        float u = 1.f / (1.f + expf(-z));
        int k = (int)ceilf(u * (float)EE);
        k = k < 1 ? 1 : (k > EE ? EE : k);
        int s = t & SMASK;
#pragma unroll
        for (int e = 0; e < EE; e++) {
            int ie = ((e - s) & 3) + 1;
            float c = (k >= ie) ? (u / (float)ie) : 0.f;
            g_c[t * EE + e] = c;
            if (c != 0.f) {
                int p = atomicAdd(&g_cnt[e], 1);
                g_list[e * M_TOK + p] = t;
                g_pos[t * EE + e] = p;
            }
        }
    }
}

__global__ void init_cnt_kernel() {
    if (threadIdx.x < EE) g_cnt[threadIdx.x] = 0;
}

// ---------------------------------------------------------------------------
// fp32 -> fp16 (x)
// ---------------------------------------------------------------------------
__global__ __launch_bounds__(256) void convert_h_kernel(
    const float* __restrict__ in, __half* __restrict__ o)
{
    size_t i = ((size_t)blockIdx.x * 256 + threadIdx.x) * 4;
    float4 v = *(const float4*)(in + i);
    *(__half2*)(o + i)     = __half2(__float2half(v.x), __float2half(v.y));
    *(__half2*)(o + i + 2) = __half2(__float2half(v.z), __float2half(v.w));
}

// ---------------------------------------------------------------------------
// transpose [R,C] -> [C,R] fp16; blockIdx.z batches
// ---------------------------------------------------------------------------
__global__ __launch_bounds__(256) void transpose_h_kernel(
    const float* __restrict__ in, __half* __restrict__ o, int R, int C)
{
    __shared__ float tile[32][33];
    size_t zoff = (size_t)blockIdx.z * R * C;
    int c0 = blockIdx.x * 32, r0 = blockIdx.y * 32;
    int tx = threadIdx.x, ty = threadIdx.y;
#pragma unroll
    for (int j = 0; j < 32; j += 8)
        tile[ty + j][tx] = in[zoff + (size_t)(r0 + ty + j) * C + c0 + tx];
    __syncthreads();
#pragma unroll
    for (int j = 0; j < 32; j += 8) {
        size_t off = zoff + (size_t)(c0 + ty + j) * R + r0 + tx;
        o[off] = __float2half(tile[tx][ty + j]);
    }
}

// ---------------------------------------------------------------------------
// sparse per-expert fp16 GEMM, 256x128 CTA tile, BK=32, 4-stage cp.async.
// 8 warps as 4(M) x 2(N), 64x64 warp tiles, 128 acc regs/thread.
// Stage (24576B) = {A: 2x8KB row blocks, B: 8KB}.
// MODE1: A = x gathered via g_list[e], B = W1T_e, relu(acc+b1)*c -> H_e fp16
//        grid (M_TOK/256, FF/128, EE)
// MODE2: A = H_e compacted, B = W2T_e, C = y_e fp32. grid (DD/128, M_TOK/256, EE)
// ---------------------------------------------------------------------------
template <int MODE>
__global__ __launch_bounds__(256, 1) void gemm_kernel(
    const __half* __restrict__ Af, const __half* __restrict__ Bf,
    const float* __restrict__ bias,
    __half* __restrict__ Ch, float* __restrict__ Yo)
{
    const int KTOT = (MODE == 1) ? DD : FF;
    const int NK   = KTOT / 32;
    const uint32_t STAGE = 24576u;

    extern __shared__ char smem[];
    uint32_t sbase = smem_u32(smem);
    int* sList = (int*)(smem + 4 * STAGE);

    const int tid = threadIdx.x;
    const int lane = tid & 31;
    const int wid = tid >> 5;
    const int wm = wid >> 1;          // 0..3 -> M offset wm*64
    const int wn = wid & 1;           // 0..1 -> N offset wn*64

    const int e = blockIdx.z;
    const int n_e = g_cnt[e];
    const int mtiles = (n_e + 255) >> 8;
    const int mt = (MODE == 1) ? blockIdx.x : blockIdx.y;
    if (mt >= mtiles) return;
    const int bm = mt * 256;
    const int bn = ((MODE == 1) ? blockIdx.y : blockIdx.x) * 128;

    if (MODE == 1) {
        int idx = bm + tid;
        sList[tid] = (idx < n_e) ? g_list[e * M_TOK + idx] : 0;
        __syncthreads();
    }

    // A rows 0-255 in two 8KB blocks (offsets 0, 8192); B at 16384.
    auto load_chunk = [&](int k0, int slot) {
        uint32_t base = sbase + (uint32_t)slot * STAGE;
#pragma unroll
        for (int q = 0; q < 6; q++) {
            int lin = tid + q * 256;              // 0..1535
            const __half* src;
            uint32_t dst;
            if (lin < 1024) {                     // A: 256 rows x 4 seg16B
                int r  = lin >> 2;
                int cq = lin & 3;
                int ke = k0 + cq * 8;
                if (MODE == 1) src = Af + (size_t)sList[r] * DD + ke;
                else           src = Af + (size_t)e * M_TOK * FF + (size_t)(bm + r) * FF + ke;
                dst = tile_addr(base + (uint32_t)(r >> 7) * 8192u, r & 127, cq * 16);
            } else {                              // B: 128 rows x 4 seg16B
                int l2 = lin - 1024;
                int r  = l2 >> 2;
                int cq = l2 & 3;
                int ke = k0 + cq * 8;
                if (MODE == 1) src = Bf + ((size_t)e * FF + bn + r) * DD + ke;
                else           src = Bf + (size_t)(bn + r) * N1 + e * FF + ke;
                dst = tile_addr(base + 16384u, r, cq * 16);
            }
            CP16(dst, src);
        }
        CP_COMMIT();
    };

    float acc[4][8][4];
#pragma unroll
    for (int mi = 0; mi < 4; mi++)
#pragma unroll
        for (int ni = 0; ni < 8; ni++)
#pragma unroll
            for (int j = 0; j < 4; j++) acc[mi][ni][j] = 0.f;

    load_chunk(0, 0);
    load_chunk(32, 1);
    load_chunk(64, 2);

    // A x4: lanes 0-15 rows (lane&15) k0-chunk; 16-31 same rows k8-chunk
    const int a_row = lane & 15;
    const int a_cbo = ((lane >> 4) & 1) * 16;
    // B x4 (two n8 frags): row_l = ((lane>>4)&1)*8 + (lane&7); cbo = ((lane>>3)&1)*16
    const int b_row = ((lane >> 4) & 1) * 8 + (lane & 7);
    const int b_cbo = ((lane >> 3) & 1) * 16;

    for (int i = 0; i < NK; i++) {
        CP_WAIT(2);
        __syncthreads();
        if (i + 3 < NK) load_chunk((i + 3) * 32, (i + 3) & 3);

        uint32_t base = sbase + (uint32_t)(i & 3) * STAGE;
        uint32_t bB = base + 16384u;

#pragma unroll
        for (int ks = 0; ks < 2; ks++) {
            int kb = ks * 32;
            uint32_t aa[4][4], bb[4][4];
#pragma unroll
            for (int mi = 0; mi < 4; mi++) {
                int r = wm * 64 + mi * 16 + a_row;
                LDMX4(aa[mi], tile_addr(base + (uint32_t)(r >> 7) * 8192u, r & 127, kb + a_cbo));
            }
#pragma unroll
            for (int np = 0; np < 4; np++) {
                int r = wn * 64 + np * 16 + b_row;
                LDMX4(bb[np], tile_addr(bB, r, kb + b_cbo));
            }
#pragma unroll
            for (int mi = 0; mi < 4; mi++)
#pragma unroll
                for (int np = 0; np < 4; np++) {
                    MMA16816(acc[mi][np * 2],     aa[mi], (&bb[np][0]));
                    MMA16816(acc[mi][np * 2 + 1], aa[mi], (&bb[np][2]));
                }
        }
    }
    CP_WAIT(0);
    __syncthreads();

    // acc(mi,ni,j): row = wm*64+mi*16+(lane>>2)+(j>>1)*8
    //               col = wn*64+ni*8+(lane&3)*2+(j&1)
    if (MODE == 1) {
        float bv[8][2];
#pragma unroll
        for (int ni = 0; ni < 8; ni++) {
            int c0 = wn * 64 + ni * 8 + (lane & 3) * 2;
            bv[ni][0] = bias[(size_t)e * FF + bn + c0];
            bv[ni][1] = bias[(size_t)e * FF + bn + c0 + 1];
        }
#pragma unroll
        for (int mi = 0; mi < 4; mi++)
#pragma unroll
            for (int h = 0; h < 2; h++) {
                int row = wm * 64 + mi * 16 + (lane >> 2) + h * 8;
                float cv = (bm + row < n_e) ? g_c[sList[row] * EE + e] : 0.f;
#pragma unroll
                for (int ni = 0; ni < 8; ni++) {
                    int c0 = wn * 64 + ni * 8 + (lane & 3) * 2;
                    float v0 = fmaxf(acc[mi][ni][h * 2 + 0] + bv[ni][0], 0.f) * cv;
                    float v1 = fmaxf(acc[mi][ni][h * 2 + 1] + bv[ni][1], 0.f) * cv;
                    *(__half2*)(smem + row * 256 + c0 * 2) =
                        __half2(__float2half(v0), __float2half(v1));
                }
            }
        __syncthreads();
#pragma unroll
        for (int q = 0; q < 16; q++) {
            int lin = tid + q * 256;              // 0..4095
            int r   = lin >> 4;
            int cw  = lin & 15;
            uint4 v = *(uint4*)(smem + r * 256 + cw * 16);
            *(uint4*)(Ch + (size_t)e * M_TOK * FF + (size_t)(bm + r) * FF + bn + cw * 8) = v;
        }
    } else {
        // fp32 epilogue in two 64KB passes (rows 0-127 then 128-255)
#pragma unroll
        for (int pass = 0; pass < 2; pass++) {
            if ((wm >> 1) == pass) {
#pragma unroll
                for (int mi = 0; mi < 4; mi++)
#pragma unroll
                    for (int h = 0; h < 2; h++) {
                        int row = (wm & 1) * 64 + mi * 16 + (lane >> 2) + h * 8;
#pragma unroll
                        for (int ni = 0; ni < 8; ni++) {
                            int c0 = wn * 64 + ni * 8 + (lane & 3) * 2;
                            *(float*)(smem + row * 512 + c0 * 4)       = acc[mi][ni][h * 2 + 0];
                            *(float*)(smem + row * 512 + (c0 + 1) * 4) = acc[mi][ni][h * 2 + 1];
                        }
                    }
            }
            __syncthreads();
#pragma unroll
            for (int q = 0; q < 16; q++) {
                int lin = tid + q * 256;          // 0..4095
                int r   = lin >> 5;
                int cw  = lin & 31;
                uint4 v = *(uint4*)(smem + r * 512 + cw * 16);
                *(uint4*)(Yo + (size_t)e * M_TOK * DD +
                          (size_t)(bm + pass * 128 + r) * DD + bn + cw * 4) = v;
            }
            if (pass == 0) __syncthreads();
        }
    }
}

// ---------------------------------------------------------------------------
// final gather: out[t] = sum over active e of (y_e[pos] + c_e*b2_e)
// ---------------------------------------------------------------------------
__global__ __launch_bounds__(256) void gather_out_kernel(
    const float* __restrict__ y, const float* __restrict__ b2,
    float* __restrict__ out)
{
    int t = blockIdx.x;
    int d = threadIdx.x * 4;
    float acc0 = 0.f, acc1 = 0.f, acc2 = 0.f, acc3 = 0.f;
#pragma unroll
    for (int e = 0; e < EE; e++) {
        float c = g_c[t * EE + e];
        if (c != 0.f) {
            int pos = g_pos[t * EE + e];
            float4 vy = *(const float4*)(y + (size_t)e * M_TOK * DD + (size_t)pos * DD + d);
            float4 vb = *(const float4*)(b2 + e * DD + d);
            acc0 += vy.x + c * vb.x;
            acc1 += vy.y + c * vb.y;
            acc2 += vy.z + c * vb.z;
            acc3 += vy.w + c * vb.w;
        }
    }
    float4 o = {acc0, acc1, acc2, acc3};
    *(float4*)(out + (size_t)t * DD + d) = o;
}

// ---------------------------------------------------------------------------
// launch. Inputs: x, W1, b1, W2, b2, Wu, bu
// ---------------------------------------------------------------------------
extern "C" void kernel_launch(void* const* d_in, const int* in_sizes, int n_in,
                              void* d_out, int out_size)
{
    const float* x  = (const float*)d_in[0];
    const float* W1 = (const float*)d_in[1];
    const float* b1 = (const float*)d_in[2];
    const float* W2 = (const float*)d_in[3];
    const float* b2 = (const float*)d_in[4];
    const float* Wu = (const float*)d_in[5];
    const float* bu = (const float*)d_in[6];
    float* out = (float*)d_out;
    (void)in_sizes; (void)n_in; (void)out_size;

    __half *xf, *w1, *w2, *H;
    float* y;
    cudaGetSymbolAddress((void**)&xf, g_x);
    cudaGetSymbolAddress((void**)&w1, g_w1);
    cudaGetSymbolAddress((void**)&w2, g_w2);
    cudaGetSymbolAddress((void**)&H,  g_H);
    cudaGetSymbolAddress((void**)&y,  g_y);

    const int SMEM_GEMM = 4 * 24576 + 1024;   // 99328
    cudaFuncSetAttribute(gemm_kernel<1>,
                         cudaFuncAttributeMaxDynamicSharedMemorySize, SMEM_GEMM);
    cudaFuncSetAttribute(gemm_kernel<2>,
                         cudaFuncAttributeMaxDynamicSharedMemorySize, SMEM_GEMM);

    init_cnt_kernel<<<1, 32>>>();
    coeff_kernel<<<M_TOK / 8, 256>>>(x, Wu, bu);

    convert_h_kernel<<<(M_TOK * DD) / (256 * 4), 256>>>(x, xf);
    {   // W1 [E][D,F] -> [E*F, D] fp16
        dim3 grid(FF / 32, DD / 32, EE);
        transpose_h_kernel<<<grid, dim3(32, 8)>>>(W1, w1, DD, FF);
    }
    {   // W2 [E*F, D] -> [D, E*F] fp16
        dim3 grid(DD / 32, N1 / 32, 1);
        transpose_h_kernel<<<grid, dim3(32, 8)>>>(W2, w2, N1, DD);
    }

    {   // GEMM1 sparse: per-expert [n_e,1024] x [1024,4096] -> H_e fp16
        dim3 grid(M_TOK / 256, FF / 128, EE);   // Mtile fast (B-panel reuse)
        gemm_kernel<1><<<grid, 256, SMEM_GEMM>>>(xf, w1, b1, H, nullptr);
    }
    {   // GEMM2 sparse: per-expert [n_e,4096] x [4096,1024] -> y_e fp32
        dim3 grid(DD / 128, M_TOK / 256, EE);   // Ntile fast (A-panel reuse)
        gemm_kernel<2><<<grid, 256, SMEM_GEMM>>>(H, w2, nullptr, nullptr, y);
    }

    gather_out_kernel<<<M_TOK, 256>>>(y, b2, out);
}

// round 10
// speedup vs baseline: 12.7444x; 1.1533x over previous
#include <cuda_runtime.h>
#include <cuda_fp16.h>
#include <math.h>
#include <stdint.h>

// ---------------- problem constants ----------------
#define M_TOK 8192
#define DD    1024
#define FF    4096
#define EE    4
#define N1    16384
#define SMASK 2047

// ---------------- scratch (__device__ globals; no allocs allowed) ----------
__device__ float   g_c [M_TOK * EE];
__device__ int     g_cnt[EE];
__device__ int     g_list[EE * M_TOK];
__device__ int     g_pos[M_TOK * EE];
__device__ __half  g_x [(size_t)M_TOK * DD];
__device__ __half  g_w1[(size_t)EE * DD * FF];     // fp16, native [E][D][F]
__device__ __half  g_w2[(size_t)N1 * DD];          // fp16, native [E*F][D]
__device__ __half  g_H [(size_t)EE * M_TOK * FF];
__device__ float   g_y [(size_t)EE * M_TOK * DD];

// ---------------- helpers ----------------
__device__ __forceinline__ uint32_t smem_u32(const void* p) {
    uint32_t a;
    asm("{ .reg .u64 t; cvta.to.shared.u64 t, %1; cvt.u32.u64 %0, t; }" : "=r"(a) : "l"(p));
    return a;
}
#define CP16(sm, g)   asm volatile("cp.async.cg.shared.global [%0], [%1], 16;" :: "r"(sm), "l"(g) : "memory")
#define CP_COMMIT()   asm volatile("cp.async.commit_group;" ::: "memory")
#define CP_WAIT(n)    asm volatile("cp.async.wait_group %0;" :: "n"(n) : "memory")

#define LDMX4(r, a) asm volatile( \
    "ldmatrix.sync.aligned.m8n8.x4.shared.b16 {%0,%1,%2,%3}, [%4];" \
    : "=r"((r)[0]), "=r"((r)[1]), "=r"((r)[2]), "=r"((r)[3]) : "r"(a))
#define LDMX4T(r, a) asm volatile( \
    "ldmatrix.sync.aligned.m8n8.x4.trans.shared.b16 {%0,%1,%2,%3}, [%4];" \
    : "=r"((r)[0]), "=r"((r)[1]), "=r"((r)[2]), "=r"((r)[3]) : "r"(a))
#define MMA16816(d, a, b) asm volatile( \
    "mma.sync.aligned.m16n8k16.row.col.f32.f16.f16.f32 " \
    "{%0,%1,%2,%3}, {%4,%5,%6,%7}, {%8,%9}, {%0,%1,%2,%3};" \
    : "+f"((d)[0]), "+f"((d)[1]), "+f"((d)[2]), "+f"((d)[3]) \
    : "r"((a)[0]), "r"((a)[1]), "r"((a)[2]), "r"((a)[3]), "r"((b)[0]), "r"((b)[1]))

// A tile: 256 rows x 128B (64 k fp16). swizzle chunk(16B) ^ (row&7).
__device__ __forceinline__ uint32_t a_addr(uint32_t base, int r, int kb) {
    return base + (uint32_t)r * 128u + ((uint32_t)(((kb >> 4) ^ (r & 7)) & 7) << 4);
}
// B tile: 64 k-rows x 256B (128 n fp16). chunk(16B,0..15): low3 ^ (k&7).
__device__ __forceinline__ uint32_t b_addr(uint32_t base, int k, int chunk) {
    uint32_t ch = (uint32_t)((chunk & 8) | ((chunk ^ k) & 7));
    return base + (uint32_t)k * 256u + (ch << 4);
}

// ---------------------------------------------------------------------------
// coeff + list build fused (g_cnt zeroed first)
// ---------------------------------------------------------------------------
__global__ __launch_bounds__(256) void coeff_kernel(
    const float* __restrict__ x, const float* __restrict__ Wu,
    const float* __restrict__ bu)
{
    int t = blockIdx.x * 8 + (threadIdx.x >> 5);
    int lane = threadIdx.x & 31;
    if (t >= M_TOK) return;
    const float4* xr = (const float4*)(x + (size_t)t * DD);
    const float4* wr = (const float4*)Wu;
    float sum = 0.f;
#pragma unroll
    for (int i = lane; i < DD / 4; i += 32) {
        float4 a = xr[i], b = wr[i];
        sum += a.x * b.x + a.y * b.y + a.z * b.z + a.w * b.w;
    }
#pragma unroll
    for (int o = 16; o; o >>= 1) sum += __shfl_xor_sync(0xffffffffu, sum, o);
    if (lane == 0) {
        float z = sum + bu[0];
        float u = 1.f / (1.f + expf(-z));
        int k = (int)ceilf(u * (float)EE);
        k = k < 1 ? 1 : (k > EE ? EE : k);
        int s = t & SMASK;
#pragma unroll
        for (int e = 0; e < EE; e++) {
            int ie = ((e - s) & 3) + 1;
            float c = (k >= ie) ? (u / (float)ie) : 0.f;
            g_c[t * EE + e] = c;
            if (c != 0.f) {
                int p = atomicAdd(&g_cnt[e], 1);
                g_list[e * M_TOK + p] = t;
                g_pos[t * EE + e] = p;
            }
        }
    }
}

__global__ void init_cnt_kernel() {
    if (threadIdx.x < EE) g_cnt[threadIdx.x] = 0;
}

// ---------------------------------------------------------------------------
// fp32 -> fp16 elementwise (layout preserved)
// ---------------------------------------------------------------------------
__global__ __launch_bounds__(256) void convert_h_kernel(
    const float* __restrict__ in, __half* __restrict__ o)
{
    size_t i = ((size_t)blockIdx.x * 256 + threadIdx.x) * 4;
    float4 v = *(const float4*)(in + i);
    *(__half2*)(o + i)     = __half2(__float2half(v.x), __float2half(v.y));
    *(__half2*)(o + i + 2) = __half2(__float2half(v.z), __float2half(v.w));
}

// ---------------------------------------------------------------------------
// sparse per-expert fp16 GEMM, 256x128 CTA tile, BK=64, 4-stage cp.async.
// 8 warps 4(M)x2(N), 64x64 warp tiles. B loaded k-major-rows/n-contiguous and
// fragmented via ldmatrix.trans (no weight pre-transpose needed).
// Stage (49152B) = {A: 256x128B = 32KB, B: 64x256B = 16KB}.
// MODE1: A = x gathered via g_list[e], B = W1[e] ([D][F]), relu(acc+b1)*c -> H_e
//        grid (M_TOK/256, FF/128, e)
// MODE2: A = H_e compacted, B = W2[e] ([F][D]), C = y_e fp32.
//        grid (DD/128, M_TOK/256, e)
// ---------------------------------------------------------------------------
template <int MODE>
__global__ __launch_bounds__(256, 1) void gemm_kernel(
    const __half* __restrict__ Af, const __half* __restrict__ Bf,
    const float* __restrict__ bias,
    __half* __restrict__ Ch, float* __restrict__ Yo)
{
    const int KTOT = (MODE == 1) ? DD : FF;
    const int NK   = KTOT / 64;
    const uint32_t STAGE = 49152u;

    extern __shared__ char smem[];
    uint32_t sbase = smem_u32(smem);
    int* sList = (int*)(smem + 4 * STAGE);

    const int tid = threadIdx.x;
    const int lane = tid & 31;
    const int wid = tid >> 5;
    const int wm = wid >> 1;          // 0..3 -> M offset wm*64
    const int wn = wid & 1;           // 0..1 -> N offset wn*64

    const int e = blockIdx.z;
    const int n_e = g_cnt[e];
    const int mtiles = (n_e + 255) >> 8;
    const int mt = (MODE == 1) ? blockIdx.x : blockIdx.y;
    if (mt >= mtiles) return;
    const int bm = mt * 256;
    const int bn = ((MODE == 1) ? blockIdx.y : blockIdx.x) * 128;

    if (MODE == 1) {
        int idx = bm + tid;
        sList[tid] = (idx < n_e) ? g_list[e * M_TOK + idx] : 0;
        __syncthreads();
    }

    auto load_chunk = [&](int k0, int slot) {
        uint32_t base = sbase + (uint32_t)slot * STAGE;
#pragma unroll
        for (int q = 0; q < 12; q++) {
            int lin = tid + q * 256;              // 0..3071
            const __half* src;
            uint32_t dst;
            if (lin < 2048) {                     // A: 256 rows x 8 seg16B
                int r  = lin >> 3;
                int cq = lin & 7;
                int ke = k0 + cq * 8;
                if (MODE == 1) src = Af + (size_t)sList[r] * DD + ke;
                else           src = Af + (size_t)e * M_TOK * FF + (size_t)(bm + r) * FF + ke;
                dst = a_addr(base, r, cq * 16);
            } else {                              // B: 64 k-rows x 16 seg16B
                int l2 = lin - 2048;
                int k  = l2 >> 4;
                int cq = l2 & 15;
                if (MODE == 1)
                    src = Bf + (size_t)e * DD * FF + (size_t)(k0 + k) * FF + bn + cq * 8;
                else
                    src = Bf + (size_t)(e * FF + k0 + k) * DD + bn + cq * 8;
                dst = b_addr(base + 32768u, k, cq);
            }
            CP16(dst, src);
        }
        CP_COMMIT();
    };

    float acc[4][8][4];
#pragma unroll
    for (int mi = 0; mi < 4; mi++)
#pragma unroll
        for (int ni = 0; ni < 8; ni++)
#pragma unroll
            for (int j = 0; j < 4; j++) acc[mi][ni][j] = 0.f;

    load_chunk(0, 0);
    load_chunk(64, 1);
    load_chunk(128, 2);

    const int a_row = lane & 15;
    const int a_sel = ((lane >> 4) & 1) * 16;     // 16B half within k16
    const int bt_k  = lane & 15;                  // trans: k within k16
    const int bt_n8 = (lane >> 4) & 1;            // n8 group select

    for (int i = 0; i < NK; i++) {
        CP_WAIT(2);
        __syncthreads();
        if (i + 3 < NK) load_chunk((i + 3) * 64, (i + 3) & 3);

        uint32_t base = sbase + (uint32_t)(i & 3) * STAGE;
        uint32_t bB = base + 32768u;

#pragma unroll
        for (int ks = 0; ks < 4; ks++) {
            uint32_t aa[4][4], bb[4][4];
#pragma unroll
            for (int mi = 0; mi < 4; mi++) {
                int r = wm * 64 + mi * 16 + a_row;
                LDMX4(aa[mi], a_addr(base, r, ks * 32 + a_sel));
            }
#pragma unroll
            for (int np = 0; np < 4; np++) {
                int k = ks * 16 + bt_k;
                int chunk = wn * 8 + np * 2 + bt_n8;
                LDMX4T(bb[np], b_addr(bB, k, chunk));
            }
#pragma unroll
            for (int mi = 0; mi < 4; mi++)
#pragma unroll
                for (int np = 0; np < 4; np++) {
                    MMA16816(acc[mi][np * 2],     aa[mi], (&bb[np][0]));
                    MMA16816(acc[mi][np * 2 + 1], aa[mi], (&bb[np][2]));
                }
        }
    }
    CP_WAIT(0);
    __syncthreads();

    // acc(mi,ni,j): row = wm*64+mi*16+(lane>>2)+(j>>1)*8
    //               col = wn*64+ni*8+(lane&3)*2+(j&1)
    if (MODE == 1) {
        float bv[8][2];
#pragma unroll
        for (int ni = 0; ni < 8; ni++) {
            int c0 = wn * 64 + ni * 8 + (lane & 3) * 2;
            bv[ni][0] = bias[(size_t)e * FF + bn + c0];
            bv[ni][1] = bias[(size_t)e * FF + bn + c0 + 1];
        }
#pragma unroll
        for (int mi = 0; mi < 4; mi++)
#pragma unroll
            for (int h = 0; h < 2; h++) {
                int row = wm * 64 + mi * 16 + (lane >> 2) + h * 8;
                float cv = (bm + row < n_e) ? g_c[sList[row] * EE + e] : 0.f;
#pragma unroll
                for (int ni = 0; ni < 8; ni++) {
                    int c0 = wn * 64 + ni * 8 + (lane & 3) * 2;
                    float v0 = fmaxf(acc[mi][ni][h * 2 + 0] + bv[ni][0], 0.f) * cv;
                    float v1 = fmaxf(acc[mi][ni][h * 2 + 1] + bv[ni][1], 0.f) * cv;
                    *(__half2*)(smem + row * 256 + c0 * 2) =
                        __half2(__float2half(v0), __float2half(v1));
                }
            }
        __syncthreads();
#pragma unroll
        for (int q = 0; q < 16; q++) {
            int lin = tid + q * 256;              // 0..4095
            int r   = lin >> 4;
            int cw  = lin & 15;
            uint4 v = *(uint4*)(smem + r * 256 + cw * 16);
            *(uint4*)(Ch + (size_t)e * M_TOK * FF + (size_t)(bm + r) * FF + bn + cw * 8) = v;
        }
    } else {
        // fp32 epilogue in two 64KB passes (rows 0-127 then 128-255)
#pragma unroll
        for (int pass = 0; pass < 2; pass++) {
            if ((wm >> 1) == pass) {
#pragma unroll
                for (int mi = 0; mi < 4; mi++)
#pragma unroll
                    for (int h = 0; h < 2; h++) {
                        int row = (wm & 1) * 64 + mi * 16 + (lane >> 2) + h * 8;
#pragma unroll
                        for (int ni = 0; ni < 8; ni++) {
                            int c0 = wn * 64 + ni * 8 + (lane & 3) * 2;
                            *(float*)(smem + row * 512 + c0 * 4)       = acc[mi][ni][h * 2 + 0];
                            *(float*)(smem + row * 512 + (c0 + 1) * 4) = acc[mi][ni][h * 2 + 1];
                        }
                    }
            }
            __syncthreads();
#pragma unroll
            for (int q = 0; q < 16; q++) {
                int lin = tid + q * 256;
                int r   = lin >> 5;
                int cw  = lin & 31;
                uint4 v = *(uint4*)(smem + r * 512 + cw * 16);
                *(uint4*)(Yo + (size_t)e * M_TOK * DD +
                          (size_t)(bm + pass * 128 + r) * DD + bn + cw * 4) = v;
            }
            if (pass == 0) __syncthreads();
        }
    }
}

// ---------------------------------------------------------------------------
// final gather: out[t] = sum over active e of (y_e[pos] + c_e*b2_e)
// ---------------------------------------------------------------------------
__global__ __launch_bounds__(256) void gather_out_kernel(
    const float* __restrict__ y, const float* __restrict__ b2,
    float* __restrict__ out)
{
    int t = blockIdx.x;
    int d = threadIdx.x * 4;
    float acc0 = 0.f, acc1 = 0.f, acc2 = 0.f, acc3 = 0.f;
#pragma unroll
    for (int e = 0; e < EE; e++) {
        float c = g_c[t * EE + e];
        if (c != 0.f) {
            int pos = g_pos[t * EE + e];
            float4 vy = *(const float4*)(y + (size_t)e * M_TOK * DD + (size_t)pos * DD + d);
            float4 vb = *(const float4*)(b2 + e * DD + d);
            acc0 += vy.x + c * vb.x;
            acc1 += vy.y + c * vb.y;
            acc2 += vy.z + c * vb.z;
            acc3 += vy.w + c * vb.w;
        }
    }
    float4 o = {acc0, acc1, acc2, acc3};
    *(float4*)(out + (size_t)t * DD + d) = o;
}

// ---------------------------------------------------------------------------
// launch. Inputs: x, W1, b1, W2, b2, Wu, bu
// ---------------------------------------------------------------------------
extern "C" void kernel_launch(void* const* d_in, const int* in_sizes, int n_in,
                              void* d_out, int out_size)
{
    const float* x  = (const float*)d_in[0];
    const float* W1 = (const float*)d_in[1];
    const float* b1 = (const float*)d_in[2];
    const float* W2 = (const float*)d_in[3];
    const float* b2 = (const float*)d_in[4];
    const float* Wu = (const float*)d_in[5];
    const float* bu = (const float*)d_in[6];
    float* out = (float*)d_out;
    (void)in_sizes; (void)n_in; (void)out_size;

    __half *xf, *w1, *w2, *H;
    float* y;
    cudaGetSymbolAddress((void**)&xf, g_x);
    cudaGetSymbolAddress((void**)&w1, g_w1);
    cudaGetSymbolAddress((void**)&w2, g_w2);
    cudaGetSymbolAddress((void**)&H,  g_H);
    cudaGetSymbolAddress((void**)&y,  g_y);

    const int SMEM_GEMM = 4 * 49152 + 1024;   // 197632
    cudaFuncSetAttribute(gemm_kernel<1>,
                         cudaFuncAttributeMaxDynamicSharedMemorySize, SMEM_GEMM);
    cudaFuncSetAttribute(gemm_kernel<2>,
                         cudaFuncAttributeMaxDynamicSharedMemorySize, SMEM_GEMM);

    init_cnt_kernel<<<1, 32>>>();
    coeff_kernel<<<M_TOK / 8, 256>>>(x, Wu, bu);

    // converts (layout preserved — no transposes needed anymore)
    convert_h_kernel<<<(M_TOK * DD) / 1024, 256>>>(x, xf);
    convert_h_kernel<<<(EE * DD * FF) / 1024, 256>>>(W1, w1);
    convert_h_kernel<<<(N1 * DD) / 1024, 256>>>(W2, w2);

    {   // GEMM1 sparse: per-expert [n_e,1024] x [1024,4096] -> H_e fp16
        dim3 grid(M_TOK / 256, FF / 128, EE);   // Mtile fast (B-panel reuse)
        gemm_kernel<1><<<grid, 256, SMEM_GEMM>>>(xf, w1, b1, H, nullptr);
    }
    {   // GEMM2 sparse: per-expert [n_e,4096] x [4096,1024] -> y_e fp32
        dim3 grid(DD / 128, M_TOK / 256, EE);   // Ntile fast (A-panel reuse)
        gemm_kernel<2><<<grid, 256, SMEM_GEMM>>>(H, w2, nullptr, nullptr, y);
    }

    gather_out_kernel<<<M_TOK, 256>>>(y, b2, out);
}

// round 15
// speedup vs baseline: 12.8788x; 1.0105x over previous
#include <cuda_runtime.h>
#include <cuda_fp16.h>
#include <math.h>
#include <stdint.h>

// ---------------- problem constants ----------------
#define M_TOK 8192
#define DD    1024
#define FF    4096
#define EE    4
#define N1    16384
#define SMASK 2047

// ---------------- scratch (__device__ globals; no allocs allowed) ----------
__device__ float   g_c [M_TOK * EE];
__device__ int     g_cnt[EE];
__device__ int     g_list[EE * M_TOK];
__device__ int     g_pos[M_TOK * EE];
__device__ __half  g_x [(size_t)M_TOK * DD];
__device__ __half  g_w1[(size_t)EE * DD * FF];     // fp16, native [E][D][F]
__device__ __half  g_w2[(size_t)N1 * DD];          // fp16, native [E*F][D]
__device__ __half  g_H [(size_t)EE * M_TOK * FF];
__device__ float   g_y [(size_t)EE * M_TOK * DD];

// ---------------- helpers ----------------
__device__ __forceinline__ uint32_t smem_u32(const void* p) {
    uint32_t a;
    asm("{ .reg .u64 t; cvta.to.shared.u64 t, %1; cvt.u32.u64 %0, t; }" : "=r"(a) : "l"(p));
    return a;
}
#define CP16(sm, g)   asm volatile("cp.async.cg.shared.global [%0], [%1], 16;" :: "r"(sm), "l"(g) : "memory")
#define CP_COMMIT()   asm volatile("cp.async.commit_group;" ::: "memory")
#define CP_WAIT(n)    asm volatile("cp.async.wait_group %0;" :: "n"(n) : "memory")

#define LDMX4(r, a) asm volatile( \
    "ldmatrix.sync.aligned.m8n8.x4.shared.b16 {%0,%1,%2,%3}, [%4];" \
    : "=r"((r)[0]), "=r"((r)[1]), "=r"((r)[2]), "=r"((r)[3]) : "r"(a))
#define LDMX4T(r, a) asm volatile( \
    "ldmatrix.sync.aligned.m8n8.x4.trans.shared.b16 {%0,%1,%2,%3}, [%4];" \
    : "=r"((r)[0]), "=r"((r)[1]), "=r"((r)[2]), "=r"((r)[3]) : "r"(a))
#define MMA16816(d, a, b) asm volatile( \
    "mma.sync.aligned.m16n8k16.row.col.f32.f16.f16.f32 " \
    "{%0,%1,%2,%3}, {%4,%5,%6,%7}, {%8,%9}, {%0,%1,%2,%3};" \
    : "+f"((d)[0]), "+f"((d)[1]), "+f"((d)[2]), "+f"((d)[3]) \
    : "r"((a)[0]), "r"((a)[1]), "r"((a)[2]), "r"((a)[3]), "r"((b)[0]), "r"((b)[1]))

// A tile: 256 rows x 128B (64 k fp16). swizzle chunk(16B) ^ (row&7).
__device__ __forceinline__ uint32_t a_addr(uint32_t base, int r, int kb) {
    return base + (uint32_t)r * 128u + ((uint32_t)(((kb >> 4) ^ (r & 7)) & 7) << 4);
}
// B tile: 64 k-rows x 256B (128 n fp16). chunk(16B,0..15): low3 ^ (k&7).
__device__ __forceinline__ uint32_t b_addr(uint32_t base, int k, int chunk) {
    uint32_t ch = (uint32_t)((chunk & 8) | ((chunk ^ k) & 7));
    return base + (uint32_t)k * 256u + (ch << 4);
}

// ---------------------------------------------------------------------------
// coeff + list build + x fp16 conversion, fused (g_cnt zeroed first)
// ---------------------------------------------------------------------------
__global__ __launch_bounds__(256) void coeff_kernel(
    const float* __restrict__ x, const float* __restrict__ Wu,
    const float* __restrict__ bu, __half* __restrict__ xf)
{
    int t = blockIdx.x * 8 + (threadIdx.x >> 5);
    int lane = threadIdx.x & 31;
    if (t >= M_TOK) return;
    const float4* xr = (const float4*)(x + (size_t)t * DD);
    const float4* wr = (const float4*)Wu;
    __half2* xo = (__half2*)(xf + (size_t)t * DD);
    float sum = 0.f;
#pragma unroll
    for (int i = lane; i < DD / 4; i += 32) {
        float4 a = xr[i], b = wr[i];
        sum += a.x * b.x + a.y * b.y + a.z * b.z + a.w * b.w;
        xo[i * 2]     = __half2(__float2half(a.x), __float2half(a.y));
        xo[i * 2 + 1] = __half2(__float2half(a.z), __float2half(a.w));
    }
#pragma unroll
    for (int o = 16; o; o >>= 1) sum += __shfl_xor_sync(0xffffffffu, sum, o);
    if (lane == 0) {
        float z = sum + bu[0];
        float u = 1.f / (1.f + expf(-z));
        int k = (int)ceilf(u * (float)EE);
        k = k < 1 ? 1 : (k > EE ? EE : k);
        int s = t & SMASK;
#pragma unroll
        for (int e = 0; e < EE; e++) {
            int ie = ((e - s) & 3) + 1;
            float c = (k >= ie) ? (u / (float)ie) : 0.f;
            g_c[t * EE + e] = c;
            if (c != 0.f) {
                int p = atomicAdd(&g_cnt[e], 1);
                g_list[e * M_TOK + p] = t;
                g_pos[t * EE + e] = p;
            }
        }
    }
}

__global__ void init_cnt_kernel() {
    if (threadIdx.x < EE) g_cnt[threadIdx.x] = 0;
}

// ---------------------------------------------------------------------------
// fp32 -> fp16 elementwise, 2x float4 per thread (weights)
// ---------------------------------------------------------------------------
__global__ __launch_bounds__(256) void convert_h_kernel(
    const float* __restrict__ in, __half* __restrict__ o)
{
    size_t i = ((size_t)blockIdx.x * 256 + threadIdx.x) * 8;
    float4 v0 = *(const float4*)(in + i);
    float4 v1 = *(const float4*)(in + i + 4);
    __half2 h0(__float2half(v0.x), __float2half(v0.y));
    __half2 h1(__float2half(v0.z), __float2half(v0.w));
    __half2 h2(__float2half(v1.x), __float2half(v1.y));
    __half2 h3(__float2half(v1.z), __float2half(v1.w));
    uint4 pk;
    pk.x = *(uint32_t*)&h0; pk.y = *(uint32_t*)&h1;
    pk.z = *(uint32_t*)&h2; pk.w = *(uint32_t*)&h3;
    *(uint4*)(o + i) = pk;
}

// ---------------------------------------------------------------------------
// sparse per-expert fp16 GEMM, 256x128 CTA tile, BK=64, 4-stage cp.async.
// 8 warps 4(M)x2(N), 64x64 warp tiles. B fragments via ldmatrix.trans from
// native n-contiguous weights. Stage (49152B) = {A: 32KB, B: 16KB}.
// MODE1: A = x gathered via g_list[e], B = W1[e] ([D][F]), relu(acc+b1)*c -> H_e
// MODE2: A = H_e compacted, B = W2[e] ([F][D]), C = y_e fp32.
// ---------------------------------------------------------------------------
template <int MODE>
__global__ __launch_bounds__(256, 1) void gemm_kernel(
    const __half* __restrict__ Af, const __half* __restrict__ Bf,
    const float* __restrict__ bias,
    __half* __restrict__ Ch, float* __restrict__ Yo)
{
    const int KTOT = (MODE == 1) ? DD : FF;
    const int NK   = KTOT / 64;
    const uint32_t STAGE = 49152u;

    extern __shared__ char smem[];
    uint32_t sbase = smem_u32(smem);
    int* sList = (int*)(smem + 4 * STAGE);

    const int tid = threadIdx.x;
    const int lane = tid & 31;
    const int wid = tid >> 5;
    const int wm = wid >> 1;          // 0..3 -> M offset wm*64
    const int wn = wid & 1;           // 0..1 -> N offset wn*64

    const int e = blockIdx.z;
    const int n_e = g_cnt[e];
    const int mtiles = (n_e + 255) >> 8;
    const int mt = (MODE == 1) ? blockIdx.x : blockIdx.y;
    if (mt >= mtiles) return;
    const int bm = mt * 256;
    const int bn = ((MODE == 1) ? blockIdx.y : blockIdx.x) * 128;

    if (MODE == 1) {
        int idx = bm + tid;
        sList[tid] = (idx < n_e) ? g_list[e * M_TOK + idx] : 0;
        __syncthreads();
    }

    auto load_chunk = [&](int k0, int slot) {
        uint32_t base = sbase + (uint32_t)slot * STAGE;
#pragma unroll
        for (int q = 0; q < 12; q++) {
            int lin = tid + q * 256;              // 0..3071
            const __half* src;
            uint32_t dst;
            if (lin < 2048) {                     // A: 256 rows x 8 seg16B
                int r  = lin >> 3;
                int cq = lin & 7;
                int ke = k0 + cq * 8;
                if (MODE == 1) src = Af + (size_t)sList[r] * DD + ke;
                else           src = Af + (size_t)e * M_TOK * FF + (size_t)(bm + r) * FF + ke;
                dst = a_addr(base, r, cq * 16);
            } else {                              // B: 64 k-rows x 16 seg16B
                int l2 = lin - 2048;
                int k  = l2 >> 4;
                int cq = l2 & 15;
                if (MODE == 1)
                    src = Bf + (size_t)e * DD * FF + (size_t)(k0 + k) * FF + bn + cq * 8;
                else
                    src = Bf + (size_t)(e * FF + k0 + k) * DD + bn + cq * 8;
                dst = b_addr(base + 32768u, k, cq);
            }
            CP16(dst, src);
        }
        CP_COMMIT();
    };

    float acc[4][8][4];
#pragma unroll
    for (int mi = 0; mi < 4; mi++)
#pragma unroll
        for (int ni = 0; ni < 8; ni++)
#pragma unroll
            for (int j = 0; j < 4; j++) acc[mi][ni][j] = 0.f;

    load_chunk(0, 0);
    load_chunk(64, 1);
    load_chunk(128, 2);

    const int a_row = lane & 15;
    const int a_sel = ((lane >> 4) & 1) * 16;     // 16B half within k16
    const int bt_k  = lane & 15;                  // trans: k within k16
    const int bt_n8 = (lane >> 4) & 1;            // n8 group select

    for (int i = 0; i < NK; i++) {
        CP_WAIT(2);
        __syncthreads();
        if (i + 3 < NK) load_chunk((i + 3) * 64, (i + 3) & 3);

        uint32_t base = sbase + (uint32_t)(i & 3) * STAGE;
        uint32_t bB = base + 32768u;

#pragma unroll
        for (int ks = 0; ks < 4; ks++) {
            uint32_t aa[4][4], bb[4][4];
#pragma unroll
            for (int mi = 0; mi < 4; mi++) {
                int r = wm * 64 + mi * 16 + a_row;
                LDMX4(aa[mi], a_addr(base, r, ks * 32 + a_sel));
            }
#pragma unroll
            for (int np = 0; np < 4; np++) {
                int k = ks * 16 + bt_k;
                int chunk = wn * 8 + np * 2 + bt_n8;
                LDMX4T(bb[np], b_addr(bB, k, chunk));
            }
#pragma unroll
            for (int mi = 0; mi < 4; mi++)
#pragma unroll
                for (int np = 0; np < 4; np++) {
                    MMA16816(acc[mi][np * 2],     aa[mi], (&bb[np][0]));
                    MMA16816(acc[mi][np * 2 + 1], aa[mi], (&bb[np][2]));
                }
        }
    }
    CP_WAIT(0);
    __syncthreads();

    // acc(mi,ni,j): row = wm*64+mi*16+(lane>>2)+(j>>1)*8
    //               col = wn*64+ni*8+(lane&3)*2+(j&1)
    if (MODE == 1) {
        float bv[8][2];
#pragma unroll
        for (int ni = 0; ni < 8; ni++) {
            int c0 = wn * 64 + ni * 8 + (lane & 3) * 2;
            bv[ni][0] = bias[(size_t)e * FF + bn + c0];
            bv[ni][1] = bias[(size_t)e * FF + bn + c0 + 1];
        }
#pragma unroll
        for (int mi = 0; mi < 4; mi++)
#pragma unroll
            for (int h = 0; h < 2; h++) {
                int row = wm * 64 + mi * 16 + (lane >> 2) + h * 8;
                float cv = (bm + row < n_e) ? g_c[sList[row] * EE + e] : 0.f;
#pragma unroll
                for (int ni = 0; ni < 8; ni++) {
                    int c0 = wn * 64 + ni * 8 + (lane & 3) * 2;
                    float v0 = fmaxf(acc[mi][ni][h * 2 + 0] + bv[ni][0], 0.f) * cv;
                    float v1 = fmaxf(acc[mi][ni][h * 2 + 1] + bv[ni][1], 0.f) * cv;
                    *(__half2*)(smem + row * 256 + c0 * 2) =
                        __half2(__float2half(v0), __float2half(v1));
                }
            }
        __syncthreads();
#pragma unroll
        for (int q = 0; q < 16; q++) {
            int lin = tid + q * 256;              // 0..4095
            int r   = lin >> 4;
            int cw  = lin & 15;
            uint4 v = *(uint4*)(smem + r * 256 + cw * 16);
            *(uint4*)(Ch + (size_t)e * M_TOK * FF + (size_t)(bm + r) * FF + bn + cw * 8) = v;
        }
    } else {
        // fp32 epilogue in two 64KB passes (rows 0-127 then 128-255)
#pragma unroll
        for (int pass = 0; pass < 2; pass++) {
            if ((wm >> 1) == pass) {
#pragma unroll
                for (int mi = 0; mi < 4; mi++)
#pragma unroll
                    for (int h = 0; h < 2; h++) {
                        int row = (wm & 1) * 64 + mi * 16 + (lane >> 2) + h * 8;
#pragma unroll
                        for (int ni = 0; ni < 8; ni++) {
                            int c0 = wn * 64 + ni * 8 + (lane & 3) * 2;
                            *(float*)(smem + row * 512 + c0 * 4)       = acc[mi][ni][h * 2 + 0];
                            *(float*)(smem + row * 512 + (c0 + 1) * 4) = acc[mi][ni][h * 2 + 1];
                        }
                    }
            }
            __syncthreads();
#pragma unroll
            for (int q = 0; q < 16; q++) {
                int lin = tid + q * 256;
                int r   = lin >> 5;
                int cw  = lin & 31;
                uint4 v = *(uint4*)(smem + r * 512 + cw * 16);
                *(uint4*)(Yo + (size_t)e * M_TOK * DD +
                          (size_t)(bm + pass * 128 + r) * DD + bn + cw * 4) = v;
            }
            if (pass == 0) __syncthreads();
        }
    }
}

// ---------------------------------------------------------------------------
// final gather: out[t] = sum over active e of (y_e[pos] + c_e*b2_e)
// ---------------------------------------------------------------------------
__global__ __launch_bounds__(256) void gather_out_kernel(
    const float* __restrict__ y, const float* __restrict__ b2,
    float* __restrict__ out)
{
    int t = blockIdx.x;
    int d = threadIdx.x * 4;
    float acc0 = 0.f, acc1 = 0.f, acc2 = 0.f, acc3 = 0.f;
#pragma unroll
    for (int e = 0; e < EE; e++) {
        float c = g_c[t * EE + e];
        if (c != 0.f) {
            int pos = g_pos[t * EE + e];
            float4 vy = *(const float4*)(y + (size_t)e * M_TOK * DD + (size_t)pos * DD + d);
            float4 vb = *(const float4*)(b2 + e * DD + d);
            acc0 += vy.x + c * vb.x;
            acc1 += vy.y + c * vb.y;
            acc2 += vy.z + c * vb.z;
            acc3 += vy.w + c * vb.w;
        }
    }
    float4 o = {acc0, acc1, acc2, acc3};
    *(float4*)(out + (size_t)t * DD + d) = o;
}

// ---------------------------------------------------------------------------
// launch. Inputs: x, W1, b1, W2, b2, Wu, bu
// ---------------------------------------------------------------------------
extern "C" void kernel_launch(void* const* d_in, const int* in_sizes, int n_in,
                              void* d_out, int out_size)
{
    const float* x  = (const float*)d_in[0];
    const float* W1 = (const float*)d_in[1];
    const float* b1 = (const float*)d_in[2];
    const float* W2 = (const float*)d_in[3];
    const float* b2 = (const float*)d_in[4];
    const float* Wu = (const float*)d_in[5];
    const float* bu = (const float*)d_in[6];
    float* out = (float*)d_out;
    (void)in_sizes; (void)n_in; (void)out_size;

    __half *xf, *w1, *w2, *H;
    float* y;
    cudaGetSymbolAddress((void**)&xf, g_x);
    cudaGetSymbolAddress((void**)&w1, g_w1);
    cudaGetSymbolAddress((void**)&w2, g_w2);
    cudaGetSymbolAddress((void**)&H,  g_H);
    cudaGetSymbolAddress((void**)&y,  g_y);

    const int SMEM_GEMM = 4 * 49152 + 1024;   // 197632
    cudaFuncSetAttribute(gemm_kernel<1>,
                         cudaFuncAttributeMaxDynamicSharedMemorySize, SMEM_GEMM);
    cudaFuncSetAttribute(gemm_kernel<2>,
                         cudaFuncAttributeMaxDynamicSharedMemorySize, SMEM_GEMM);

    init_cnt_kernel<<<1, 32>>>();
    // coeff + list build + x fp16 conversion (one pass over x)
    coeff_kernel<<<M_TOK / 8, 256>>>(x, Wu, bu, xf);

    // weight converts (layout preserved), 8 floats/thread
    convert_h_kernel<<<(EE * DD * FF) / 2048, 256>>>(W1, w1);
    convert_h_kernel<<<(N1 * DD) / 2048, 256>>>(W2, w2);

    {   // GEMM1 sparse: per-expert [n_e,1024] x [1024,4096] -> H_e fp16
        dim3 grid(M_TOK / 256, FF / 128, EE);   // Mtile fast (B-panel reuse)
        gemm_kernel<1><<<grid, 256, SMEM_GEMM>>>(xf, w1, b1, H, nullptr);
    }
    {   // GEMM2 sparse: per-expert [n_e,4096] x [4096,1024] -> y_e fp32
        dim3 grid(DD / 128, M_TOK / 256, EE);   // Ntile fast (A-panel reuse)
        gemm_kernel<2><<<grid, 256, SMEM_GEMM>>>(H, w2, nullptr, nullptr, y);
    }

    gather_out_kernel<<<M_TOK, 256>>>(y, b2, out);
}